// round 2
// baseline (speedup 1.0000x reference)
#include <cuda_runtime.h>
#include <math.h>

// Problem constants
#define BB    8
#define CC    256
#define HH    64
#define WW    64
#define NROW  32768          // B*H*W
#define INTER 1024
#define KCB   1024

typedef unsigned long long ull;

// ---------------- scratch (device globals; no allocation at runtime) --------
__device__ float g_A0[NROW * CC];        // activation ping (NHWC rows)
__device__ float g_A1[NROW * CC];        // activation pong
__device__ float g_LN[NROW * CC];        // conv+LN output
__device__ float g_C [NROW * INTER];     // fc1/gelu output
__device__ float g_grn[BB * INTER];      // GRN sum of squares
__device__ float g_scl[BB * INTER];      // GRN nx per (b, k)
__device__ float g_r [NROW];             // row norms of encoder output
__device__ float g_cn[KCB];              // codebook row norms
__device__ ull   g_best[NROW];           // packed argmin per row

// ---------------- XLA-style reductions ---------------------------------------
__device__ __forceinline__ float warp_red(float v) {
    #pragma unroll
    for (int off = 16; off > 0; off >>= 1)
        v = __fadd_rn(v, __shfl_down_sync(0xffffffffu, v, off));
    return v;
}

// 256-thread block row reduction: per-warp shfl tree over 32 contiguous
// elements, then cross-warp tree over 8 partials (zero-padded, exact).
__device__ float block_red256(float v, float* s) {
    int t = threadIdx.x, w = t >> 5, l = t & 31;
    float ws = warp_red(v);
    if (l == 0) s[w] = ws;
    __syncthreads();
    if (w == 0) {
        float p = (l < 8) ? s[l] : 0.0f;
        p = warp_red(p);
        if (l == 0) s[8] = p;
    }
    __syncthreads();
    float r = s[8];
    __syncthreads();
    return r;
}

// ---------------- transpose: per-batch [R,S] -> [S,R] (layout only) ----------
__global__ void k_transpose(const float* __restrict__ in, float* __restrict__ out,
                            int R, int S) {
    __shared__ float tile[32][33];
    int b = blockIdx.z;
    int base = b * R * S;
    int s0 = blockIdx.x * 32, r0 = blockIdx.y * 32;
    int sx = s0 + threadIdx.x;
    for (int i = threadIdx.y; i < 32; i += 8)
        tile[i][threadIdx.x] = in[base + (r0 + i) * S + sx];
    __syncthreads();
    int rx = r0 + threadIdx.x;
    for (int i = threadIdx.y; i < 32; i += 8)
        out[base + (s0 + i) * R + rx] = tile[threadIdx.x][i];
}

// ---------------- depthwise conv 7x7 (+bias after) + LayerNorm ---------------
__global__ void k_conv_ln(const float* __restrict__ in, float* __restrict__ out,
                          const float* __restrict__ cw, const float* __restrict__ cb,
                          const float* __restrict__ lng, const float* __restrict__ lnb) {
    __shared__ float red[16];
    int p = blockIdx.x;
    int c = threadIdx.x;
    int b = p >> 12;
    int hw = p & 4095;
    int h = hw >> 6, w = hw & 63;
    const float* base = in + ((long)b << 12) * CC;

    float acc = 0.0f;   // ascending-tap FFMA chain; zero-pad taps are exact no-ops
    #pragma unroll
    for (int kh = 0; kh < 7; kh++) {
        int hh = h + kh - 3;
        if ((unsigned)hh >= 64u) continue;
        #pragma unroll
        for (int kw = 0; kw < 7; kw++) {
            int ww = w + kw - 3;
            if ((unsigned)ww >= 64u) continue;
            acc = __fmaf_rn(cw[c * 49 + kh * 7 + kw],
                            base[((hh << 6) + ww) * CC + c], acc);
        }
    }
    float y = __fadd_rn(acc, cb[c]);          // bias is a separate add in the ref

    float mu = __fmul_rn(block_red256(y, red), 0.00390625f);
    float d  = __fsub_rn(y, mu);
    float var = __fmul_rn(block_red256(__fmul_rn(d, d), red), 0.00390625f);
    float rs = rsqrtf(__fadd_rn(var, 1e-5f));
    float o  = __fadd_rn(__fmul_rn(__fmul_rn(d, rs), lng[c]), lnb[c]);
    out[p * CC + c] = o;
}

// ---------------- fc1 GEMM [32768,256]x[256,1024] + exact GELU ---------------
__global__ void k_fc1(const float* __restrict__ A, const float* __restrict__ Wm,
                      const float* __restrict__ bias, float* __restrict__ Out) {
    __shared__ float As[16][65];
    __shared__ float Bs[16][65];
    int t = threadIdx.x;
    int tx = t & 15, ty = t >> 4;
    int rowBase = blockIdx.y * 64, colBase = blockIdx.x * 64;
    float acc[4][4] = {};
    int ar = t >> 2, ak = (t & 3) * 4;
    int bk = t >> 4, bn = (t & 15) * 4;
    for (int k0 = 0; k0 < 256; k0 += 16) {
        float4 av = *(const float4*)(A + (rowBase + ar) * 256 + k0 + ak);
        As[ak + 0][ar] = av.x; As[ak + 1][ar] = av.y;
        As[ak + 2][ar] = av.z; As[ak + 3][ar] = av.w;
        float4 bv = *(const float4*)(Wm + (k0 + bk) * 1024 + colBase + bn);
        Bs[bk][bn + 0] = bv.x; Bs[bk][bn + 1] = bv.y;
        Bs[bk][bn + 2] = bv.z; Bs[bk][bn + 3] = bv.w;
        __syncthreads();
        #pragma unroll
        for (int kk = 0; kk < 16; kk++) {
            float a[4], bvv[4];
            #pragma unroll
            for (int i = 0; i < 4; i++) a[i] = As[kk][ty * 4 + i];
            #pragma unroll
            for (int j = 0; j < 4; j++) bvv[j] = Bs[kk][tx * 4 + j];
            #pragma unroll
            for (int i = 0; i < 4; i++)
                #pragma unroll
                for (int j = 0; j < 4; j++)
                    acc[i][j] = __fmaf_rn(a[i], bvv[j], acc[i][j]);
        }
        __syncthreads();
    }
    #pragma unroll
    for (int i = 0; i < 4; i++)
        #pragma unroll
        for (int j = 0; j < 4; j++) {
            int col = colBase + tx * 4 + j;
            float y = __fadd_rn(acc[i][j], bias[col]);
            // gelu exact: x * (erf(x/sqrt2) + 1) / 2
            float e = erff(__fdiv_rn(y, 1.4142135623730951f));
            float u = __fadd_rn(e, 1.0f);
            float g = 0.5f * __fmul_rn(y, u);
            Out[(rowBase + ty * 4 + i) * 1024 + col] = g;
        }
}

// ---------------- GRN sum of squares (XLA column-reduce emulation) -----------
// grid (32 chan-groups, 8 batches), block (32,32). 32 stride-32 sequential
// partials per channel, then smem halving tree.
__global__ void k_grn_sumsq(const float* __restrict__ C, float* __restrict__ S) {
    __shared__ float sm[32][33];
    int b = blockIdx.y;
    int c = blockIdx.x * 32 + threadIdx.x;
    int ty = threadIdx.y;
    const float* base = C + ((long)b << 12) * 1024 + c;
    float acc = 0.0f;
    for (int tt = 0; tt < 128; tt++) {
        float v = base[(ty + (tt << 5)) * 1024];
        acc = __fadd_rn(acc, __fmul_rn(v, v));
    }
    sm[ty][threadIdx.x] = acc;
    __syncthreads();
    #pragma unroll
    for (int off = 16; off > 0; off >>= 1) {
        if (ty < off)
            sm[ty][threadIdx.x] = __fadd_rn(sm[ty][threadIdx.x], sm[ty + off][threadIdx.x]);
        __syncthreads();
    }
    if (ty == 0) S[b * 1024 + c] = sm[0][threadIdx.x];
}

// ---------------- GRN nx: gx = sqrt(S); nx = gx / (mean(gx) + eps) -----------
__global__ void k_grn_nx(const float* __restrict__ S, float* __restrict__ nxo) {
    __shared__ float s[40];
    int b = blockIdx.x, t = threadIdx.x, w = t >> 5, l = t & 31;
    float gx = sqrtf(S[b * 1024 + t]);
    float ws = warp_red(gx);
    if (l == 0) s[w] = ws;
    __syncthreads();
    if (w == 0) {
        float p = s[l];
        p = warp_red(p);
        if (l == 0) s[33] = p;
    }
    __syncthreads();
    float mean = __fmul_rn(s[33], 0.0009765625f);
    nxo[b * 1024 + t] = __fdiv_rn(gx, __fadd_rn(mean, 1e-6f));
}

// ---------------- fc2 GEMM with exact GRN chain at A-load + bias + residual --
__global__ void k_fc2(const float* __restrict__ A, const float* __restrict__ Wm,
                      const float* __restrict__ nx, const float* __restrict__ gg,
                      const float* __restrict__ gb, const float* __restrict__ b2,
                      const float* __restrict__ res, float* __restrict__ Out) {
    __shared__ float As[16][65];
    __shared__ float Bs[16][65];
    int t = threadIdx.x;
    int tx = t & 15, ty = t >> 4;
    int rowBase = blockIdx.y * 64, colBase = blockIdx.x * 64;
    int bidx = rowBase >> 12;
    float acc[4][4] = {};
    int ar = t >> 2, ak = (t & 3) * 4;
    int bk = t >> 4, bn = (t & 15) * 4;
    for (int k0 = 0; k0 < 1024; k0 += 16) {
        float4 av = *(const float4*)(A + (rowBase + ar) * 1024 + k0 + ak);
        const float* nxp = nx + bidx * 1024 + k0 + ak;
        const float* ggp = gg + k0 + ak;
        const float* gbp = gb + k0 + ak;
        float yy[4] = {av.x, av.y, av.z, av.w};
        #pragma unroll
        for (int q = 0; q < 4; q++) {
            // z = gg*(y*nx) + gb + y, with per-op rounding as in the ref
            float t1 = __fmul_rn(yy[q], nxp[q]);
            t1 = __fmul_rn(ggp[q], t1);
            t1 = __fadd_rn(t1, gbp[q]);
            yy[q] = __fadd_rn(t1, yy[q]);
        }
        As[ak + 0][ar] = yy[0]; As[ak + 1][ar] = yy[1];
        As[ak + 2][ar] = yy[2]; As[ak + 3][ar] = yy[3];
        float4 bv = *(const float4*)(Wm + (k0 + bk) * 256 + colBase + bn);
        Bs[bk][bn + 0] = bv.x; Bs[bk][bn + 1] = bv.y;
        Bs[bk][bn + 2] = bv.z; Bs[bk][bn + 3] = bv.w;
        __syncthreads();
        #pragma unroll
        for (int kk = 0; kk < 16; kk++) {
            float a[4], bvv[4];
            #pragma unroll
            for (int i = 0; i < 4; i++) a[i] = As[kk][ty * 4 + i];
            #pragma unroll
            for (int j = 0; j < 4; j++) bvv[j] = Bs[kk][tx * 4 + j];
            #pragma unroll
            for (int i = 0; i < 4; i++)
                #pragma unroll
                for (int j = 0; j < 4; j++)
                    acc[i][j] = __fmaf_rn(a[i], bvv[j], acc[i][j]);
        }
        __syncthreads();
    }
    #pragma unroll
    for (int i = 0; i < 4; i++)
        #pragma unroll
        for (int j = 0; j < 4; j++) {
            int row = rowBase + ty * 4 + i;
            int col = colBase + tx * 4 + j;
            float o = __fadd_rn(acc[i][j], b2[col]);
            Out[row * 256 + col] = __fadd_rn(o, res[row * 256 + col]);
        }
}

// ---------------- 256-element row sum-of-squares (XLA row-reduce) ------------
__global__ void k_rownorm256(const float* __restrict__ X, float* __restrict__ R) {
    __shared__ float red[16];
    int n = blockIdx.x, c = threadIdx.x;
    float v = X[n * 256 + c];
    float s = block_red256(__fmul_rn(v, v), red);
    if (c == 0) R[n] = s;
}

// ---------------- VQ: d2 = fl(fl(r - 2m) + cn), argmin w/ first-index ties ---
__global__ void k_vq(const float* __restrict__ A, const float* __restrict__ CB,
                     const float* __restrict__ rr, const float* __restrict__ cn,
                     ull* __restrict__ best) {
    __shared__ float As[16][65];
    __shared__ float Bs[16][65];
    __shared__ ull sbest[64];
    int t = threadIdx.x;
    int tx = t & 15, ty = t >> 4;
    int rowBase = blockIdx.y * 64, colBase = blockIdx.x * 64;
    if (t < 64) sbest[t] = ~0ull;
    float acc[4][4] = {};
    int ar = t >> 2, ak = (t & 3) * 4;
    int lc = t >> 2, kd = (t & 3) * 4;
    for (int k0 = 0; k0 < 256; k0 += 16) {
        float4 av = *(const float4*)(A + (rowBase + ar) * 256 + k0 + ak);
        As[ak + 0][ar] = av.x; As[ak + 1][ar] = av.y;
        As[ak + 2][ar] = av.z; As[ak + 3][ar] = av.w;
        float4 bv = *(const float4*)(CB + (colBase + lc) * 256 + k0 + kd);
        Bs[kd + 0][lc] = bv.x; Bs[kd + 1][lc] = bv.y;
        Bs[kd + 2][lc] = bv.z; Bs[kd + 3][lc] = bv.w;
        __syncthreads();
        #pragma unroll
        for (int kk = 0; kk < 16; kk++) {
            float a[4], bvv[4];
            #pragma unroll
            for (int i = 0; i < 4; i++) a[i] = As[kk][ty * 4 + i];
            #pragma unroll
            for (int j = 0; j < 4; j++) bvv[j] = Bs[kk][tx * 4 + j];
            #pragma unroll
            for (int i = 0; i < 4; i++)
                #pragma unroll
                for (int j = 0; j < 4; j++)
                    acc[i][j] = __fmaf_rn(a[i], bvv[j], acc[i][j]);
        }
        __syncthreads();
    }
    #pragma unroll
    for (int i = 0; i < 4; i++) {
        float rrow = rr[rowBase + ty * 4 + i];
        ull mykey = ~0ull;
        #pragma unroll
        for (int j = 0; j < 4; j++) {
            int code = colBase + tx * 4 + j;
            float m2 = __fmul_rn(2.0f, acc[i][j]);
            float t1 = __fsub_rn(rrow, m2);
            float d2 = __fadd_rn(t1, cn[code]);       // d2 > 0 -> bits monotone
            ull key = ((ull)__float_as_uint(d2) << 32) | (unsigned)code;
            if (key < mykey) mykey = key;
        }
        atomicMin(&sbest[ty * 4 + i], mykey);
    }
    __syncthreads();
    if (t < 64) atomicMin(&best[rowBase + t], sbest[t]);
}

// ---------------- gather quantized (exact straight-through fp32) -------------
__global__ void k_vq_gather(const ull* __restrict__ best, const float* __restrict__ CB,
                            const float* __restrict__ enc, float* __restrict__ qn,
                            float* __restrict__ out_idx) {
    int n = blockIdx.x, c = threadIdx.x;
    int k = (int)(unsigned)(best[n] & 0xFFFFFFFFull);
    float q = CB[k * 256 + c];
    float inp = enc[n * 256 + c];
    qn[n * 256 + c] = __fsub_rn(__fadd_rn(q, inp), inp);
    if (c == 0) out_idx[n] = (float)k;
}

// ---------------- host side ---------------------------------------------------
static void run_block(const float* cur, float* nxt, const float* const* p, int off, int d,
                      float* LN, float* Cbuf, float* grn, float* nx) {
    const float* cw  = p[off + 0] + d * 256 * 49;
    const float* cbi = p[off + 1] + d * 256;
    const float* lng = p[off + 2] + d * 256;
    const float* lnb = p[off + 3] + d * 256;
    const float* w1  = p[off + 4] + d * 256 * 1024;
    const float* b1  = p[off + 5] + d * 1024;
    const float* gg  = p[off + 6] + d * 1024;
    const float* gb  = p[off + 7] + d * 1024;
    const float* w2  = p[off + 8] + d * 1024 * 256;
    const float* b2  = p[off + 9] + d * 256;
    k_conv_ln<<<NROW, 256>>>(cur, LN, cw, cbi, lng, lnb);
    k_fc1<<<dim3(16, 512), 256>>>(LN, w1, b1, Cbuf);
    k_grn_sumsq<<<dim3(32, 8), dim3(32, 32)>>>(Cbuf, grn);
    k_grn_nx<<<BB, 1024>>>(grn, nx);
    k_fc2<<<dim3(4, 512), 256>>>(Cbuf, w2, nx, gg, gb, b2, cur, nxt);
}

extern "C" void kernel_launch(void* const* d_in, const int* in_sizes, int n_in,
                              void* d_out, int out_size) {
    const float* x  = (const float*)d_in[0];
    const float* cb = (const float*)d_in[1];
    const float* p[20];
    for (int i = 0; i < 20; i++) p[i] = (const float*)d_in[2 + i];
    float* out = (float*)d_out;

    float *A0, *A1, *LN, *Cbuf, *grn, *nx, *rr, *cn;
    ull* best;
    cudaGetSymbolAddress((void**)&A0,   g_A0);
    cudaGetSymbolAddress((void**)&A1,   g_A1);
    cudaGetSymbolAddress((void**)&LN,   g_LN);
    cudaGetSymbolAddress((void**)&Cbuf, g_C);
    cudaGetSymbolAddress((void**)&grn,  g_grn);
    cudaGetSymbolAddress((void**)&nx,   g_scl);
    cudaGetSymbolAddress((void**)&rr,   g_r);
    cudaGetSymbolAddress((void**)&cn,   g_cn);
    cudaGetSymbolAddress((void**)&best, g_best);

    dim3 tt(32, 8);
    // x NCHW -> NHWC
    k_transpose<<<dim3(128, 8, 8), tt>>>(x, A0, 256, 4096);

    float* cur = A0;
    float* nxt = A1;
    for (int d = 0; d < 2; d++) {
        run_block(cur, nxt, p, 0, d, LN, Cbuf, grn, nx);
        float* tmp = cur; cur = nxt; nxt = tmp;
    }
    // vector quantization
    k_rownorm256<<<NROW, 256>>>(cur, rr);
    k_rownorm256<<<KCB, 256>>>(cb, cn);
    cudaMemsetAsync(best, 0xFF, NROW * sizeof(ull));
    k_vq<<<dim3(16, 512), 256>>>(cur, cb, rr, cn, best);
    k_vq_gather<<<NROW, 256>>>(best, cb, cur, nxt, out + 2 * NROW * CC);
    // quantized NHWC -> NCHW
    k_transpose<<<dim3(8, 128, 8), tt>>>(nxt, out, 4096, 256);
    cur = nxt;
    nxt = (cur == A0) ? A1 : A0;
    // decoder
    for (int d = 0; d < 2; d++) {
        run_block(cur, nxt, p, 10, d, LN, Cbuf, grn, nx);
        float* tmp = cur; cur = nxt; nxt = tmp;
    }
    // decoded NHWC -> NCHW
    k_transpose<<<dim3(8, 128, 8), tt>>>(cur, out + NROW * CC, 4096, 256);
}

// round 3
// speedup vs baseline: 1.3064x; 1.3064x over previous
#include <cuda_runtime.h>
#include <math.h>

// Problem constants
#define BB    8
#define CC    256
#define NROW  32768          // B*H*W
#define INTER 1024
#define KCB   1024

typedef unsigned long long ull;

// ---------------- scratch (device globals; no allocation at runtime) --------
__device__ float g_A0[NROW * CC];
__device__ float g_A1[NROW * CC];
__device__ float g_LN[NROW * CC];
__device__ float g_C [NROW * INTER];
__device__ float g_grn[BB * INTER];
__device__ float g_scl[BB * INTER];      // GRN nx per (b, k)
__device__ float g_r [NROW];
__device__ float g_cn[KCB];
__device__ ull   g_best[NROW];

// ---------------- packed fp32x2 FMA (bit-identical per lane to FFMA) --------
__device__ __forceinline__ ull dup2(float a) {
    ull r; asm("mov.b64 %0, {%1, %1};" : "=l"(r) : "f"(a)); return r;
}
__device__ __forceinline__ void fma2(float2& d, ull a2, const float2& b) {
    ull& dd = reinterpret_cast<ull&>(d);
    asm("fma.rn.f32x2 %0, %1, %2, %0;"
        : "+l"(dd)
        : "l"(a2), "l"(reinterpret_cast<const ull&>(b)));
}

// ---------------- XLA-style reductions (verified bit-exact; do not touch) ---
__device__ __forceinline__ float warp_red(float v) {
    #pragma unroll
    for (int off = 16; off > 0; off >>= 1)
        v = __fadd_rn(v, __shfl_down_sync(0xffffffffu, v, off));
    return v;
}

__device__ float block_red256(float v, float* s) {
    int t = threadIdx.x, w = t >> 5, l = t & 31;
    float ws = warp_red(v);
    if (l == 0) s[w] = ws;
    __syncthreads();
    if (w == 0) {
        float p = (l < 8) ? s[l] : 0.0f;
        p = warp_red(p);
        if (l == 0) s[8] = p;
    }
    __syncthreads();
    float r = s[8];
    __syncthreads();
    return r;
}

// ---------------- transpose: per-batch [R,S] -> [S,R] ------------------------
__global__ void k_transpose(const float* __restrict__ in, float* __restrict__ out,
                            int R, int S) {
    __shared__ float tile[32][33];
    int b = blockIdx.z;
    int base = b * R * S;
    int s0 = blockIdx.x * 32, r0 = blockIdx.y * 32;
    int sx = s0 + threadIdx.x;
    for (int i = threadIdx.y; i < 32; i += 8)
        tile[i][threadIdx.x] = in[base + (r0 + i) * S + sx];
    __syncthreads();
    int rx = r0 + threadIdx.x;
    for (int i = threadIdx.y; i < 32; i += 8)
        out[base + (s0 + i) * R + rx] = tile[threadIdx.x][i];
}

// ---------------- depthwise conv 7x7 + bias + LayerNorm (bit-exact) ----------
__global__ void k_conv_ln(const float* __restrict__ in, float* __restrict__ out,
                          const float* __restrict__ cw, const float* __restrict__ cb,
                          const float* __restrict__ lng, const float* __restrict__ lnb) {
    __shared__ float red[16];
    int p = blockIdx.x;
    int c = threadIdx.x;
    int b = p >> 12;
    int hw = p & 4095;
    int h = hw >> 6, w = hw & 63;
    const float* base = in + ((long)b << 12) * CC;

    float acc = 0.0f;
    #pragma unroll
    for (int kh = 0; kh < 7; kh++) {
        int hh = h + kh - 3;
        if ((unsigned)hh >= 64u) continue;
        #pragma unroll
        for (int kw = 0; kw < 7; kw++) {
            int ww = w + kw - 3;
            if ((unsigned)ww >= 64u) continue;
            acc = __fmaf_rn(cw[c * 49 + kh * 7 + kw],
                            base[((hh << 6) + ww) * CC + c], acc);
        }
    }
    float y = __fadd_rn(acc, cb[c]);

    float mu = __fmul_rn(block_red256(y, red), 0.00390625f);
    float d  = __fsub_rn(y, mu);
    float var = __fmul_rn(block_red256(__fmul_rn(d, d), red), 0.00390625f);
    float rs = rsqrtf(__fadd_rn(var, 1e-5f));
    out[p * CC + c] = __fadd_rn(__fmul_rn(__fmul_rn(d, rs), lng[c]), lnb[c]);
}

// ============================================================================
// GEMM core: 128x64 CTA tile, 256 threads, 8x4 per thread, BK=16,
// double-buffered smem, packed f32x2 accumulation (bit-exact k-ascending).
// ============================================================================
#define BM 128
#define BN 64
#define BK 16
#define APAD 4

// ---------------- fc1: [32768,256] x [256,1024] + exact GELU ----------------
__global__ __launch_bounds__(256)
void k_fc1(const float* __restrict__ A, const float* __restrict__ Wm,
           const float* __restrict__ bias, float* __restrict__ Out) {
    __shared__ float As[2][BK][BM + APAD];
    __shared__ float Bs[2][BK][BN];
    const int K = 256, N = 1024;
    int t = threadIdx.x;
    int tx4 = (t & 15) * 4, ty8 = (t >> 4) * 8;
    int rowBase = blockIdx.y * BM, colBase = blockIdx.x * BN;
    int ar = t >> 1, ak = (t & 1) * 8;
    int bk = t >> 4, bn = (t & 15) * 4;

    const float* Ap = A + (size_t)(rowBase + ar) * K + ak;
    const float* Bp = Wm + (size_t)bk * N + colBase + bn;

    float2 acc[8][2];
    #pragma unroll
    for (int i = 0; i < 8; i++) { acc[i][0] = make_float2(0.f, 0.f); acc[i][1] = make_float2(0.f, 0.f); }

    float4 ra0 = *(const float4*)(Ap);
    float4 ra1 = *(const float4*)(Ap + 4);
    float4 rb  = *(const float4*)(Bp);

    const int nk = K / BK;
    #pragma unroll 1
    for (int kt = 0; kt < nk; kt++) {
        int cur = kt & 1;
        // stage current regs -> smem[cur]
        As[cur][ak + 0][ar] = ra0.x; As[cur][ak + 1][ar] = ra0.y;
        As[cur][ak + 2][ar] = ra0.z; As[cur][ak + 3][ar] = ra0.w;
        As[cur][ak + 4][ar] = ra1.x; As[cur][ak + 5][ar] = ra1.y;
        As[cur][ak + 6][ar] = ra1.z; As[cur][ak + 7][ar] = ra1.w;
        *(float4*)&Bs[cur][bk][bn] = rb;
        __syncthreads();
        if (kt + 1 < nk) {
            ra0 = *(const float4*)(Ap + (kt + 1) * BK);
            ra1 = *(const float4*)(Ap + (kt + 1) * BK + 4);
            rb  = *(const float4*)(Bp + (size_t)(kt + 1) * BK * N);
        }
        #pragma unroll
        for (int kk = 0; kk < BK; kk++) {
            float4 a0 = *(const float4*)&As[cur][kk][ty8];
            float4 a1 = *(const float4*)&As[cur][kk][ty8 + 4];
            float4 bv = *(const float4*)&Bs[cur][kk][tx4];
            float2 b0 = make_float2(bv.x, bv.y), b1 = make_float2(bv.z, bv.w);
            ull ap;
            ap = dup2(a0.x); fma2(acc[0][0], ap, b0); fma2(acc[0][1], ap, b1);
            ap = dup2(a0.y); fma2(acc[1][0], ap, b0); fma2(acc[1][1], ap, b1);
            ap = dup2(a0.z); fma2(acc[2][0], ap, b0); fma2(acc[2][1], ap, b1);
            ap = dup2(a0.w); fma2(acc[3][0], ap, b0); fma2(acc[3][1], ap, b1);
            ap = dup2(a1.x); fma2(acc[4][0], ap, b0); fma2(acc[4][1], ap, b1);
            ap = dup2(a1.y); fma2(acc[5][0], ap, b0); fma2(acc[5][1], ap, b1);
            ap = dup2(a1.z); fma2(acc[6][0], ap, b0); fma2(acc[6][1], ap, b1);
            ap = dup2(a1.w); fma2(acc[7][0], ap, b0); fma2(acc[7][1], ap, b1);
        }
        __syncthreads();
    }

    float4 bia = *(const float4*)(bias + colBase + tx4);
    float bb[4] = {bia.x, bia.y, bia.z, bia.w};
    #pragma unroll
    for (int i = 0; i < 8; i++) {
        float v[4] = {acc[i][0].x, acc[i][0].y, acc[i][1].x, acc[i][1].y};
        float4 o;
        float* op = &o.x;
        #pragma unroll
        for (int j = 0; j < 4; j++) {
            float y = __fadd_rn(v[j], bb[j]);
            float e = erff(__fdiv_rn(y, 1.4142135623730951f));
            float u = __fadd_rn(e, 1.0f);
            op[j] = 0.5f * __fmul_rn(y, u);
        }
        *(float4*)(Out + (size_t)(rowBase + ty8 + i) * N + colBase + tx4) = o;
    }
}

// ---------------- GRN sum of squares (bit-exact) -----------------------------
__global__ void k_grn_sumsq(const float* __restrict__ C, float* __restrict__ S) {
    __shared__ float sm[32][33];
    int b = blockIdx.y;
    int c = blockIdx.x * 32 + threadIdx.x;
    int ty = threadIdx.y;
    const float* base = C + ((long)b << 12) * 1024 + c;
    float acc = 0.0f;
    for (int tt = 0; tt < 128; tt++) {
        float v = base[(ty + (tt << 5)) * 1024];
        acc = __fadd_rn(acc, __fmul_rn(v, v));
    }
    sm[ty][threadIdx.x] = acc;
    __syncthreads();
    #pragma unroll
    for (int off = 16; off > 0; off >>= 1) {
        if (ty < off)
            sm[ty][threadIdx.x] = __fadd_rn(sm[ty][threadIdx.x], sm[ty + off][threadIdx.x]);
        __syncthreads();
    }
    if (ty == 0) S[b * 1024 + c] = sm[0][threadIdx.x];
}

// ---------------- GRN nx (bit-exact) -----------------------------------------
__global__ void k_grn_nx(const float* __restrict__ S, float* __restrict__ nxo) {
    __shared__ float s[40];
    int b = blockIdx.x, t = threadIdx.x, w = t >> 5, l = t & 31;
    float gx = sqrtf(S[b * 1024 + t]);
    float ws = warp_red(gx);
    if (l == 0) s[w] = ws;
    __syncthreads();
    if (w == 0) {
        float p = s[l];
        p = warp_red(p);
        if (l == 0) s[33] = p;
    }
    __syncthreads();
    float mean = __fmul_rn(s[33], 0.0009765625f);
    nxo[b * 1024 + t] = __fdiv_rn(gx, __fadd_rn(mean, 1e-6f));
}

// ---------------- fc2: [32768,1024] x [1024,256], GRN at A-load --------------
__global__ __launch_bounds__(256)
void k_fc2(const float* __restrict__ A, const float* __restrict__ Wm,
           const float* __restrict__ nx, const float* __restrict__ gg,
           const float* __restrict__ gb, const float* __restrict__ b2,
           const float* __restrict__ res, float* __restrict__ Out) {
    __shared__ float As[2][BK][BM + APAD];
    __shared__ float Bs[2][BK][BN];
    const int K = 1024, N = 256;
    int t = threadIdx.x;
    int tx4 = (t & 15) * 4, ty8 = (t >> 4) * 8;
    int rowBase = blockIdx.y * BM, colBase = blockIdx.x * BN;
    int bidx = rowBase >> 12;
    int ar = t >> 1, ak = (t & 1) * 8;
    int bk = t >> 4, bn = (t & 15) * 4;

    const float* Ap  = A + (size_t)(rowBase + ar) * K + ak;
    const float* Bp  = Wm + (size_t)bk * N + colBase + bn;
    const float* nxp = nx + bidx * 1024 + ak;
    const float* ggp = gg + ak;
    const float* gbp = gb + ak;

    float2 acc[8][2];
    #pragma unroll
    for (int i = 0; i < 8; i++) { acc[i][0] = make_float2(0.f, 0.f); acc[i][1] = make_float2(0.f, 0.f); }

    float ra[8];
    {
        float4 v0 = *(const float4*)(Ap), v1 = *(const float4*)(Ap + 4);
        ra[0]=v0.x; ra[1]=v0.y; ra[2]=v0.z; ra[3]=v0.w;
        ra[4]=v1.x; ra[5]=v1.y; ra[6]=v1.z; ra[7]=v1.w;
        float4 n0 = *(const float4*)(nxp), n1 = *(const float4*)(nxp + 4);
        float4 g0 = *(const float4*)(ggp), g1 = *(const float4*)(ggp + 4);
        float4 h0 = *(const float4*)(gbp), h1 = *(const float4*)(gbp + 4);
        float nn[8] = {n0.x,n0.y,n0.z,n0.w,n1.x,n1.y,n1.z,n1.w};
        float gG[8] = {g0.x,g0.y,g0.z,g0.w,g1.x,g1.y,g1.z,g1.w};
        float gB[8] = {h0.x,h0.y,h0.z,h0.w,h1.x,h1.y,h1.z,h1.w};
        #pragma unroll
        for (int q = 0; q < 8; q++) {
            float t1 = __fmul_rn(ra[q], nn[q]);
            t1 = __fmul_rn(gG[q], t1);
            t1 = __fadd_rn(t1, gB[q]);
            ra[q] = __fadd_rn(t1, ra[q]);
        }
    }
    float4 rb = *(const float4*)(Bp);

    const int nk = K / BK;
    #pragma unroll 1
    for (int kt = 0; kt < nk; kt++) {
        int cur = kt & 1;
        #pragma unroll
        for (int q = 0; q < 8; q++) As[cur][ak + q][ar] = ra[q];
        *(float4*)&Bs[cur][bk][bn] = rb;
        __syncthreads();
        if (kt + 1 < nk) {
            int ko = (kt + 1) * BK;
            float4 v0 = *(const float4*)(Ap + ko), v1 = *(const float4*)(Ap + ko + 4);
            ra[0]=v0.x; ra[1]=v0.y; ra[2]=v0.z; ra[3]=v0.w;
            ra[4]=v1.x; ra[5]=v1.y; ra[6]=v1.z; ra[7]=v1.w;
            float4 n0 = *(const float4*)(nxp + ko), n1 = *(const float4*)(nxp + ko + 4);
            float4 g0 = *(const float4*)(ggp + ko), g1 = *(const float4*)(ggp + ko + 4);
            float4 h0 = *(const float4*)(gbp + ko), h1 = *(const float4*)(gbp + ko + 4);
            float nn[8] = {n0.x,n0.y,n0.z,n0.w,n1.x,n1.y,n1.z,n1.w};
            float gG[8] = {g0.x,g0.y,g0.z,g0.w,g1.x,g1.y,g1.z,g1.w};
            float gB[8] = {h0.x,h0.y,h0.z,h0.w,h1.x,h1.y,h1.z,h1.w};
            #pragma unroll
            for (int q = 0; q < 8; q++) {
                float t1 = __fmul_rn(ra[q], nn[q]);
                t1 = __fmul_rn(gG[q], t1);
                t1 = __fadd_rn(t1, gB[q]);
                ra[q] = __fadd_rn(t1, ra[q]);
            }
            rb = *(const float4*)(Bp + (size_t)(kt + 1) * BK * N);
        }
        #pragma unroll
        for (int kk = 0; kk < BK; kk++) {
            float4 a0 = *(const float4*)&As[cur][kk][ty8];
            float4 a1 = *(const float4*)&As[cur][kk][ty8 + 4];
            float4 bv = *(const float4*)&Bs[cur][kk][tx4];
            float2 b0 = make_float2(bv.x, bv.y), b1 = make_float2(bv.z, bv.w);
            ull ap;
            ap = dup2(a0.x); fma2(acc[0][0], ap, b0); fma2(acc[0][1], ap, b1);
            ap = dup2(a0.y); fma2(acc[1][0], ap, b0); fma2(acc[1][1], ap, b1);
            ap = dup2(a0.z); fma2(acc[2][0], ap, b0); fma2(acc[2][1], ap, b1);
            ap = dup2(a0.w); fma2(acc[3][0], ap, b0); fma2(acc[3][1], ap, b1);
            ap = dup2(a1.x); fma2(acc[4][0], ap, b0); fma2(acc[4][1], ap, b1);
            ap = dup2(a1.y); fma2(acc[5][0], ap, b0); fma2(acc[5][1], ap, b1);
            ap = dup2(a1.z); fma2(acc[6][0], ap, b0); fma2(acc[6][1], ap, b1);
            ap = dup2(a1.w); fma2(acc[7][0], ap, b0); fma2(acc[7][1], ap, b1);
        }
        __syncthreads();
    }

    float4 bia = *(const float4*)(b2 + colBase + tx4);
    float bb[4] = {bia.x, bia.y, bia.z, bia.w};
    #pragma unroll
    for (int i = 0; i < 8; i++) {
        size_t off = (size_t)(rowBase + ty8 + i) * N + colBase + tx4;
        float4 rv = *(const float4*)(res + off);
        float rr[4] = {rv.x, rv.y, rv.z, rv.w};
        float v[4] = {acc[i][0].x, acc[i][0].y, acc[i][1].x, acc[i][1].y};
        float4 o;
        float* op = &o.x;
        #pragma unroll
        for (int j = 0; j < 4; j++)
            op[j] = __fadd_rn(__fadd_rn(v[j], bb[j]), rr[j]);
        *(float4*)(Out + off) = o;
    }
}

// ---------------- row sum-of-squares (bit-exact) ------------------------------
__global__ void k_rownorm256(const float* __restrict__ X, float* __restrict__ R) {
    __shared__ float red[16];
    int n = blockIdx.x, c = threadIdx.x;
    float v = X[n * 256 + c];
    float s = block_red256(__fmul_rn(v, v), red);
    if (c == 0) R[n] = s;
}

// ---------------- VQ: scores GEMM + argmin (bit-exact d2) ---------------------
__global__ __launch_bounds__(256)
void k_vq(const float* __restrict__ A, const float* __restrict__ CB,
          const float* __restrict__ rr, const float* __restrict__ cn,
          ull* __restrict__ best) {
    __shared__ float As[2][BK][BM + APAD];
    __shared__ float Bs[2][BK][BN];
    __shared__ ull sbest[BM];
    const int K = 256, N = 1024;
    int t = threadIdx.x;
    int tx4 = (t & 15) * 4, ty8 = (t >> 4) * 8;
    int rowBase = blockIdx.y * BM, colBase = blockIdx.x * BN;
    int ar = t >> 1, ak = (t & 1) * 8;
    int lc = t >> 2, kd = (t & 3) * 4;     // B loader: codebook rows (K-major)

    if (t < BM) sbest[t] = ~0ull;

    const float* Ap = A + (size_t)(rowBase + ar) * K + ak;

    float2 acc[8][2];
    #pragma unroll
    for (int i = 0; i < 8; i++) { acc[i][0] = make_float2(0.f, 0.f); acc[i][1] = make_float2(0.f, 0.f); }

    float4 ra0 = *(const float4*)(Ap);
    float4 ra1 = *(const float4*)(Ap + 4);
    float4 rb  = *(const float4*)(CB + (size_t)(colBase + lc) * K + kd);

    const int nk = K / BK;
    #pragma unroll 1
    for (int kt = 0; kt < nk; kt++) {
        int cur = kt & 1;
        As[cur][ak + 0][ar] = ra0.x; As[cur][ak + 1][ar] = ra0.y;
        As[cur][ak + 2][ar] = ra0.z; As[cur][ak + 3][ar] = ra0.w;
        As[cur][ak + 4][ar] = ra1.x; As[cur][ak + 5][ar] = ra1.y;
        As[cur][ak + 6][ar] = ra1.z; As[cur][ak + 7][ar] = ra1.w;
        Bs[cur][kd + 0][lc] = rb.x; Bs[cur][kd + 1][lc] = rb.y;
        Bs[cur][kd + 2][lc] = rb.z; Bs[cur][kd + 3][lc] = rb.w;
        __syncthreads();
        if (kt + 1 < nk) {
            ra0 = *(const float4*)(Ap + (kt + 1) * BK);
            ra1 = *(const float4*)(Ap + (kt + 1) * BK + 4);
            rb  = *(const float4*)(CB + (size_t)(colBase + lc) * K + (kt + 1) * BK + kd);
        }
        #pragma unroll
        for (int kk = 0; kk < BK; kk++) {
            float4 a0 = *(const float4*)&As[cur][kk][ty8];
            float4 a1 = *(const float4*)&As[cur][kk][ty8 + 4];
            float4 bv = *(const float4*)&Bs[cur][kk][tx4];
            float2 b0 = make_float2(bv.x, bv.y), b1 = make_float2(bv.z, bv.w);
            ull ap;
            ap = dup2(a0.x); fma2(acc[0][0], ap, b0); fma2(acc[0][1], ap, b1);
            ap = dup2(a0.y); fma2(acc[1][0], ap, b0); fma2(acc[1][1], ap, b1);
            ap = dup2(a0.z); fma2(acc[2][0], ap, b0); fma2(acc[2][1], ap, b1);
            ap = dup2(a0.w); fma2(acc[3][0], ap, b0); fma2(acc[3][1], ap, b1);
            ap = dup2(a1.x); fma2(acc[4][0], ap, b0); fma2(acc[4][1], ap, b1);
            ap = dup2(a1.y); fma2(acc[5][0], ap, b0); fma2(acc[5][1], ap, b1);
            ap = dup2(a1.z); fma2(acc[6][0], ap, b0); fma2(acc[6][1], ap, b1);
            ap = dup2(a1.w); fma2(acc[7][0], ap, b0); fma2(acc[7][1], ap, b1);
        }
        __syncthreads();
    }

    float4 cnv = *(const float4*)(cn + colBase + tx4);
    float cc[4] = {cnv.x, cnv.y, cnv.z, cnv.w};
    #pragma unroll
    for (int i = 0; i < 8; i++) {
        float rrow = rr[rowBase + ty8 + i];
        float v[4] = {acc[i][0].x, acc[i][0].y, acc[i][1].x, acc[i][1].y};
        ull mykey = ~0ull;
        #pragma unroll
        for (int j = 0; j < 4; j++) {
            int code = colBase + tx4 + j;
            float m2 = __fmul_rn(2.0f, v[j]);
            float t1 = __fsub_rn(rrow, m2);
            float d2 = __fadd_rn(t1, cc[j]);
            ull key = ((ull)__float_as_uint(d2) << 32) | (unsigned)code;
            if (key < mykey) mykey = key;
        }
        atomicMin(&sbest[ty8 + i], mykey);
    }
    __syncthreads();
    if (t < BM) atomicMin(&best[rowBase + t], sbest[t]);
}

// ---------------- gather quantized (exact straight-through fp32) -------------
__global__ void k_vq_gather(const ull* __restrict__ best, const float* __restrict__ CB,
                            const float* __restrict__ enc, float* __restrict__ qn,
                            float* __restrict__ out_idx) {
    int n = blockIdx.x, c = threadIdx.x;
    int k = (int)(unsigned)(best[n] & 0xFFFFFFFFull);
    float q = CB[k * 256 + c];
    float inp = enc[n * 256 + c];
    qn[n * 256 + c] = __fsub_rn(__fadd_rn(q, inp), inp);
    if (c == 0) out_idx[n] = (float)k;
}

// ---------------- host side ---------------------------------------------------
static void run_block(const float* cur, float* nxt, const float* const* p, int off, int d,
                      float* LN, float* Cbuf, float* grn, float* nx) {
    const float* cw  = p[off + 0] + d * 256 * 49;
    const float* cbi = p[off + 1] + d * 256;
    const float* lng = p[off + 2] + d * 256;
    const float* lnb = p[off + 3] + d * 256;
    const float* w1  = p[off + 4] + d * 256 * 1024;
    const float* b1  = p[off + 5] + d * 1024;
    const float* gg  = p[off + 6] + d * 1024;
    const float* gb  = p[off + 7] + d * 1024;
    const float* w2  = p[off + 8] + d * 1024 * 256;
    const float* b2  = p[off + 9] + d * 256;
    k_conv_ln<<<NROW, 256>>>(cur, LN, cw, cbi, lng, lnb);
    k_fc1<<<dim3(INTER / BN, NROW / BM), 256>>>(LN, w1, b1, Cbuf);
    k_grn_sumsq<<<dim3(32, 8), dim3(32, 32)>>>(Cbuf, grn);
    k_grn_nx<<<BB, 1024>>>(grn, nx);
    k_fc2<<<dim3(CC / BN, NROW / BM), 256>>>(Cbuf, w2, nx, gg, gb, b2, cur, nxt);
}

extern "C" void kernel_launch(void* const* d_in, const int* in_sizes, int n_in,
                              void* d_out, int out_size) {
    const float* x  = (const float*)d_in[0];
    const float* cb = (const float*)d_in[1];
    const float* p[20];
    for (int i = 0; i < 20; i++) p[i] = (const float*)d_in[2 + i];
    float* out = (float*)d_out;

    float *A0, *A1, *LN, *Cbuf, *grn, *nx, *rr, *cn;
    ull* best;
    cudaGetSymbolAddress((void**)&A0,   g_A0);
    cudaGetSymbolAddress((void**)&A1,   g_A1);
    cudaGetSymbolAddress((void**)&LN,   g_LN);
    cudaGetSymbolAddress((void**)&Cbuf, g_C);
    cudaGetSymbolAddress((void**)&grn,  g_grn);
    cudaGetSymbolAddress((void**)&nx,   g_scl);
    cudaGetSymbolAddress((void**)&rr,   g_r);
    cudaGetSymbolAddress((void**)&cn,   g_cn);
    cudaGetSymbolAddress((void**)&best, g_best);

    dim3 tt(32, 8);
    k_transpose<<<dim3(128, 8, 8), tt>>>(x, A0, 256, 4096);

    float* cur = A0;
    float* nxt = A1;
    for (int d = 0; d < 2; d++) {
        run_block(cur, nxt, p, 0, d, LN, Cbuf, grn, nx);
        float* tmp = cur; cur = nxt; nxt = tmp;
    }
    k_rownorm256<<<NROW, 256>>>(cur, rr);
    k_rownorm256<<<KCB, 256>>>(cb, cn);
    cudaMemsetAsync(best, 0xFF, NROW * sizeof(ull));
    k_vq<<<dim3(KCB / BN, NROW / BM), 256>>>(cur, cb, rr, cn, best);
    k_vq_gather<<<NROW, 256>>>(best, cb, cur, nxt, out + 2 * NROW * CC);
    k_transpose<<<dim3(8, 128, 8), tt>>>(nxt, out, 4096, 256);
    cur = nxt;
    nxt = (cur == A0) ? A1 : A0;
    for (int d = 0; d < 2; d++) {
        run_block(cur, nxt, p, 10, d, LN, Cbuf, grn, nx);
        float* tmp = cur; cur = nxt; nxt = tmp;
    }
    k_transpose<<<dim3(8, 128, 8), tt>>>(cur, out + NROW * CC, 4096, 256);
}

// round 4
// speedup vs baseline: 1.3831x; 1.0587x over previous
#include <cuda_runtime.h>
#include <math.h>

// Problem constants
#define BB    8
#define CC    256
#define NROW  32768          // B*H*W
#define INTER 1024
#define KCB   1024

typedef unsigned long long ull;

// ---------------- scratch (device globals; no allocation at runtime) --------
__device__ float g_A0[NROW * CC];
__device__ float g_A1[NROW * CC];
__device__ float g_LN[NROW * CC];
__device__ float g_C [NROW * INTER];
__device__ float g_grn[BB * INTER];
__device__ float g_scl[BB * INTER];      // GRN nx per (b, k)
__device__ float g_r [NROW];
__device__ float g_cn[KCB];
__device__ ull   g_best[NROW];

// ---------------- packed fp32x2 FMA (bit-identical per lane to FFMA) --------
__device__ __forceinline__ ull dup2(float a) {
    ull r; asm("mov.b64 %0, {%1, %1};" : "=l"(r) : "f"(a)); return r;
}
__device__ __forceinline__ void fma2(float2& d, ull a2, const float2& b) {
    ull& dd = reinterpret_cast<ull&>(d);
    asm("fma.rn.f32x2 %0, %1, %2, %0;"
        : "+l"(dd)
        : "l"(a2), "l"(reinterpret_cast<const ull&>(b)));
}

// ---------------- XLA-style reductions (verified bit-exact; do not touch) ---
__device__ __forceinline__ float warp_red(float v) {
    #pragma unroll
    for (int off = 16; off > 0; off >>= 1)
        v = __fadd_rn(v, __shfl_down_sync(0xffffffffu, v, off));
    return v;
}

__device__ float block_red256(float v, float* s) {
    int t = threadIdx.x, w = t >> 5, l = t & 31;
    float ws = warp_red(v);
    if (l == 0) s[w] = ws;
    __syncthreads();
    if (w == 0) {
        float p = (l < 8) ? s[l] : 0.0f;
        p = warp_red(p);
        if (l == 0) s[8] = p;
    }
    __syncthreads();
    float r = s[8];
    __syncthreads();
    return r;
}

// ---------------- transpose: per-batch [R,S] -> [S,R] ------------------------
__global__ void k_transpose(const float* __restrict__ in, float* __restrict__ out,
                            int R, int S) {
    __shared__ float tile[32][33];
    int b = blockIdx.z;
    int base = b * R * S;
    int s0 = blockIdx.x * 32, r0 = blockIdx.y * 32;
    int sx = s0 + threadIdx.x;
    for (int i = threadIdx.y; i < 32; i += 8)
        tile[i][threadIdx.x] = in[base + (r0 + i) * S + sx];
    __syncthreads();
    int rx = r0 + threadIdx.x;
    for (int i = threadIdx.y; i < 32; i += 8)
        out[base + (s0 + i) * R + rx] = tile[threadIdx.x][i];
}

// ---------------- depthwise conv 7x7 + bias + LayerNorm (bit-exact) ----------
__global__ void k_conv_ln(const float* __restrict__ in, float* __restrict__ out,
                          const float* __restrict__ cw, const float* __restrict__ cb,
                          const float* __restrict__ lng, const float* __restrict__ lnb) {
    __shared__ float red[16];
    int p = blockIdx.x;
    int c = threadIdx.x;
    int b = p >> 12;
    int hw = p & 4095;
    int h = hw >> 6, w = hw & 63;
    const float* base = in + ((long)b << 12) * CC;

    float acc = 0.0f;
    #pragma unroll
    for (int kh = 0; kh < 7; kh++) {
        int hh = h + kh - 3;
        if ((unsigned)hh >= 64u) continue;
        #pragma unroll
        for (int kw = 0; kw < 7; kw++) {
            int ww = w + kw - 3;
            if ((unsigned)ww >= 64u) continue;
            acc = __fmaf_rn(cw[c * 49 + kh * 7 + kw],
                            base[((hh << 6) + ww) * CC + c], acc);
        }
    }
    float y = __fadd_rn(acc, cb[c]);

    float mu = __fmul_rn(block_red256(y, red), 0.00390625f);
    float d  = __fsub_rn(y, mu);
    float var = __fmul_rn(block_red256(__fmul_rn(d, d), red), 0.00390625f);
    float rs = rsqrtf(__fadd_rn(var, 1e-5f));
    out[p * CC + c] = __fadd_rn(__fmul_rn(__fmul_rn(d, rs), lng[c]), lnb[c]);
}

// ============================================================================
// GEMM core: 128x128 CTA tile, 256 threads, 8x8 per thread (two 64-col half
// groups), BK=16, double-buffered smem, packed f32x2 (bit-exact k-ascending).
// ============================================================================
#define BM 128
#define BN 128
#define BK 16
#define APAD 4
#define BPAD 4

// inner-product step for one kk: a0/a1 = 8 A-rows, b0/b1 = 8 B-cols
#define MMA_STEP(acc, a0, a1, b0, b1)                                         \
    {                                                                         \
        float2 p00 = make_float2(b0.x, b0.y), p01 = make_float2(b0.z, b0.w);  \
        float2 p10 = make_float2(b1.x, b1.y), p11 = make_float2(b1.z, b1.w);  \
        ull ap;                                                               \
        ap = dup2(a0.x); fma2(acc[0][0], ap, p00); fma2(acc[0][1], ap, p01);  \
                         fma2(acc[0][2], ap, p10); fma2(acc[0][3], ap, p11);  \
        ap = dup2(a0.y); fma2(acc[1][0], ap, p00); fma2(acc[1][1], ap, p01);  \
                         fma2(acc[1][2], ap, p10); fma2(acc[1][3], ap, p11);  \
        ap = dup2(a0.z); fma2(acc[2][0], ap, p00); fma2(acc[2][1], ap, p01);  \
                         fma2(acc[2][2], ap, p10); fma2(acc[2][3], ap, p11);  \
        ap = dup2(a0.w); fma2(acc[3][0], ap, p00); fma2(acc[3][1], ap, p01);  \
                         fma2(acc[3][2], ap, p10); fma2(acc[3][3], ap, p11);  \
        ap = dup2(a1.x); fma2(acc[4][0], ap, p00); fma2(acc[4][1], ap, p01);  \
                         fma2(acc[4][2], ap, p10); fma2(acc[4][3], ap, p11);  \
        ap = dup2(a1.y); fma2(acc[5][0], ap, p00); fma2(acc[5][1], ap, p01);  \
                         fma2(acc[5][2], ap, p10); fma2(acc[5][3], ap, p11);  \
        ap = dup2(a1.z); fma2(acc[6][0], ap, p00); fma2(acc[6][1], ap, p01);  \
                         fma2(acc[6][2], ap, p10); fma2(acc[6][3], ap, p11);  \
        ap = dup2(a1.w); fma2(acc[7][0], ap, p00); fma2(acc[7][1], ap, p01);  \
                         fma2(acc[7][2], ap, p10); fma2(acc[7][3], ap, p11);  \
    }

// ---------------- fc1: [32768,256] x [256,1024] + exact GELU ----------------
__global__ __launch_bounds__(256, 2)
void k_fc1(const float* __restrict__ A, const float* __restrict__ Wm,
           const float* __restrict__ bias, float* __restrict__ Out) {
    __shared__ float As[2][BK][BM + APAD];
    __shared__ float Bs[2][BK][BN + BPAD];
    const int K = 256, N = 1024;
    int t = threadIdx.x;
    int tx4 = (t & 15) * 4, ty8 = (t >> 4) * 8;
    int rowBase = blockIdx.y * BM, colBase = blockIdx.x * BN;
    int ar = t >> 1, ak = (t & 1) * 8;
    int bk = t >> 4, bn = (t & 15) * 4;

    const float* Ap = A + (size_t)(rowBase + ar) * K + ak;
    const float* Bp = Wm + (size_t)bk * N + colBase + bn;

    float2 acc[8][4];
    #pragma unroll
    for (int i = 0; i < 8; i++)
        #pragma unroll
        for (int j = 0; j < 4; j++) acc[i][j] = make_float2(0.f, 0.f);

    float4 ra0 = *(const float4*)(Ap);
    float4 ra1 = *(const float4*)(Ap + 4);
    float4 rb0 = *(const float4*)(Bp);
    float4 rb1 = *(const float4*)(Bp + 64);

    const int nk = K / BK;
    #pragma unroll 1
    for (int kt = 0; kt < nk; kt++) {
        int cur = kt & 1;
        As[cur][ak + 0][ar] = ra0.x; As[cur][ak + 1][ar] = ra0.y;
        As[cur][ak + 2][ar] = ra0.z; As[cur][ak + 3][ar] = ra0.w;
        As[cur][ak + 4][ar] = ra1.x; As[cur][ak + 5][ar] = ra1.y;
        As[cur][ak + 6][ar] = ra1.z; As[cur][ak + 7][ar] = ra1.w;
        *(float4*)&Bs[cur][bk][bn]      = rb0;
        *(float4*)&Bs[cur][bk][bn + 64] = rb1;
        __syncthreads();
        if (kt + 1 < nk) {
            ra0 = *(const float4*)(Ap + (kt + 1) * BK);
            ra1 = *(const float4*)(Ap + (kt + 1) * BK + 4);
            rb0 = *(const float4*)(Bp + (size_t)(kt + 1) * BK * N);
            rb1 = *(const float4*)(Bp + (size_t)(kt + 1) * BK * N + 64);
        }
        #pragma unroll
        for (int kk = 0; kk < BK; kk++) {
            float4 a0 = *(const float4*)&As[cur][kk][ty8];
            float4 a1 = *(const float4*)&As[cur][kk][ty8 + 4];
            float4 b0 = *(const float4*)&Bs[cur][kk][tx4];
            float4 b1 = *(const float4*)&Bs[cur][kk][tx4 + 64];
            MMA_STEP(acc, a0, a1, b0, b1)
        }
        __syncthreads();
    }

    float4 bi0 = *(const float4*)(bias + colBase + tx4);
    float4 bi1 = *(const float4*)(bias + colBase + tx4 + 64);
    float bb[8] = {bi0.x, bi0.y, bi0.z, bi0.w, bi1.x, bi1.y, bi1.z, bi1.w};
    #pragma unroll
    for (int i = 0; i < 8; i++) {
        float v[8] = {acc[i][0].x, acc[i][0].y, acc[i][1].x, acc[i][1].y,
                      acc[i][2].x, acc[i][2].y, acc[i][3].x, acc[i][3].y};
        float o[8];
        #pragma unroll
        for (int j = 0; j < 8; j++) {
            float y = __fadd_rn(v[j], bb[j]);
            float e = erff(__fdiv_rn(y, 1.4142135623730951f));
            float u = __fadd_rn(e, 1.0f);
            o[j] = 0.5f * __fmul_rn(y, u);
        }
        float* dst = Out + (size_t)(rowBase + ty8 + i) * N + colBase + tx4;
        *(float4*)dst        = make_float4(o[0], o[1], o[2], o[3]);
        *(float4*)(dst + 64) = make_float4(o[4], o[5], o[6], o[7]);
    }
}

// ---------------- GRN sum of squares (bit-exact) -----------------------------
__global__ void k_grn_sumsq(const float* __restrict__ C, float* __restrict__ S) {
    __shared__ float sm[32][33];
    int b = blockIdx.y;
    int c = blockIdx.x * 32 + threadIdx.x;
    int ty = threadIdx.y;
    const float* base = C + ((long)b << 12) * 1024 + c;
    float acc = 0.0f;
    for (int tt = 0; tt < 128; tt++) {
        float v = base[(ty + (tt << 5)) * 1024];
        acc = __fadd_rn(acc, __fmul_rn(v, v));
    }
    sm[ty][threadIdx.x] = acc;
    __syncthreads();
    #pragma unroll
    for (int off = 16; off > 0; off >>= 1) {
        if (ty < off)
            sm[ty][threadIdx.x] = __fadd_rn(sm[ty][threadIdx.x], sm[ty + off][threadIdx.x]);
        __syncthreads();
    }
    if (ty == 0) S[b * 1024 + c] = sm[0][threadIdx.x];
}

// ---------------- GRN nx (bit-exact) -----------------------------------------
__global__ void k_grn_nx(const float* __restrict__ S, float* __restrict__ nxo) {
    __shared__ float s[40];
    int b = blockIdx.x, t = threadIdx.x, w = t >> 5, l = t & 31;
    float gx = sqrtf(S[b * 1024 + t]);
    float ws = warp_red(gx);
    if (l == 0) s[w] = ws;
    __syncthreads();
    if (w == 0) {
        float p = s[l];
        p = warp_red(p);
        if (l == 0) s[33] = p;
    }
    __syncthreads();
    float mean = __fmul_rn(s[33], 0.0009765625f);
    nxo[b * 1024 + t] = __fdiv_rn(gx, __fadd_rn(mean, 1e-6f));
}

// ---------------- fc2: [32768,1024] x [1024,256], GRN at A-load --------------
__device__ __forceinline__ void grn_chain8(float* ra, const float* nxp,
                                           const float* ggp, const float* gbp) {
    float4 n0 = *(const float4*)(nxp), n1 = *(const float4*)(nxp + 4);
    float4 g0 = *(const float4*)(ggp), g1 = *(const float4*)(ggp + 4);
    float4 h0 = *(const float4*)(gbp), h1 = *(const float4*)(gbp + 4);
    float nn[8] = {n0.x,n0.y,n0.z,n0.w,n1.x,n1.y,n1.z,n1.w};
    float gG[8] = {g0.x,g0.y,g0.z,g0.w,g1.x,g1.y,g1.z,g1.w};
    float gB[8] = {h0.x,h0.y,h0.z,h0.w,h1.x,h1.y,h1.z,h1.w};
    #pragma unroll
    for (int q = 0; q < 8; q++) {
        float t1 = __fmul_rn(ra[q], nn[q]);
        t1 = __fmul_rn(gG[q], t1);
        t1 = __fadd_rn(t1, gB[q]);
        ra[q] = __fadd_rn(t1, ra[q]);
    }
}

__global__ __launch_bounds__(256, 2)
void k_fc2(const float* __restrict__ A, const float* __restrict__ Wm,
           const float* __restrict__ nx, const float* __restrict__ gg,
           const float* __restrict__ gb, const float* __restrict__ b2,
           const float* __restrict__ res, float* __restrict__ Out) {
    __shared__ float As[2][BK][BM + APAD];
    __shared__ float Bs[2][BK][BN + BPAD];
    const int K = 1024, N = 256;
    int t = threadIdx.x;
    int tx4 = (t & 15) * 4, ty8 = (t >> 4) * 8;
    int rowBase = blockIdx.y * BM, colBase = blockIdx.x * BN;
    int bidx = rowBase >> 12;
    int ar = t >> 1, ak = (t & 1) * 8;
    int bk = t >> 4, bn = (t & 15) * 4;

    const float* Ap  = A + (size_t)(rowBase + ar) * K + ak;
    const float* Bp  = Wm + (size_t)bk * N + colBase + bn;
    const float* nxp = nx + bidx * 1024 + ak;
    const float* ggp = gg + ak;
    const float* gbp = gb + ak;

    float2 acc[8][4];
    #pragma unroll
    for (int i = 0; i < 8; i++)
        #pragma unroll
        for (int j = 0; j < 4; j++) acc[i][j] = make_float2(0.f, 0.f);

    float ra[8];
    {
        float4 v0 = *(const float4*)(Ap), v1 = *(const float4*)(Ap + 4);
        ra[0]=v0.x; ra[1]=v0.y; ra[2]=v0.z; ra[3]=v0.w;
        ra[4]=v1.x; ra[5]=v1.y; ra[6]=v1.z; ra[7]=v1.w;
        grn_chain8(ra, nxp, ggp, gbp);
    }
    float4 rb0 = *(const float4*)(Bp);
    float4 rb1 = *(const float4*)(Bp + 64);

    const int nk = K / BK;
    #pragma unroll 1
    for (int kt = 0; kt < nk; kt++) {
        int cur = kt & 1;
        #pragma unroll
        for (int q = 0; q < 8; q++) As[cur][ak + q][ar] = ra[q];
        *(float4*)&Bs[cur][bk][bn]      = rb0;
        *(float4*)&Bs[cur][bk][bn + 64] = rb1;
        __syncthreads();
        if (kt + 1 < nk) {
            int ko = (kt + 1) * BK;
            float4 v0 = *(const float4*)(Ap + ko), v1 = *(const float4*)(Ap + ko + 4);
            ra[0]=v0.x; ra[1]=v0.y; ra[2]=v0.z; ra[3]=v0.w;
            ra[4]=v1.x; ra[5]=v1.y; ra[6]=v1.z; ra[7]=v1.w;
            grn_chain8(ra, nxp + ko, ggp + ko, gbp + ko);
            rb0 = *(const float4*)(Bp + (size_t)ko * N);
            rb1 = *(const float4*)(Bp + (size_t)ko * N + 64);
        }
        #pragma unroll
        for (int kk = 0; kk < BK; kk++) {
            float4 a0 = *(const float4*)&As[cur][kk][ty8];
            float4 a1 = *(const float4*)&As[cur][kk][ty8 + 4];
            float4 b0 = *(const float4*)&Bs[cur][kk][tx4];
            float4 b1 = *(const float4*)&Bs[cur][kk][tx4 + 64];
            MMA_STEP(acc, a0, a1, b0, b1)
        }
        __syncthreads();
    }

    float4 bi0 = *(const float4*)(b2 + colBase + tx4);
    float4 bi1 = *(const float4*)(b2 + colBase + tx4 + 64);
    float bb[8] = {bi0.x, bi0.y, bi0.z, bi0.w, bi1.x, bi1.y, bi1.z, bi1.w};
    #pragma unroll
    for (int i = 0; i < 8; i++) {
        size_t off = (size_t)(rowBase + ty8 + i) * N + colBase + tx4;
        float4 r0 = *(const float4*)(res + off);
        float4 r1 = *(const float4*)(res + off + 64);
        float rr[8] = {r0.x, r0.y, r0.z, r0.w, r1.x, r1.y, r1.z, r1.w};
        float v[8] = {acc[i][0].x, acc[i][0].y, acc[i][1].x, acc[i][1].y,
                      acc[i][2].x, acc[i][2].y, acc[i][3].x, acc[i][3].y};
        float o[8];
        #pragma unroll
        for (int j = 0; j < 8; j++)
            o[j] = __fadd_rn(__fadd_rn(v[j], bb[j]), rr[j]);
        *(float4*)(Out + off)      = make_float4(o[0], o[1], o[2], o[3]);
        *(float4*)(Out + off + 64) = make_float4(o[4], o[5], o[6], o[7]);
    }
}

// ---------------- row sum-of-squares (bit-exact) ------------------------------
__global__ void k_rownorm256(const float* __restrict__ X, float* __restrict__ R) {
    __shared__ float red[16];
    int n = blockIdx.x, c = threadIdx.x;
    float v = X[n * 256 + c];
    float s = block_red256(__fmul_rn(v, v), red);
    if (c == 0) R[n] = s;
}

// ---------------- VQ: scores GEMM + argmin (bit-exact d2) ---------------------
__global__ __launch_bounds__(256, 2)
void k_vq(const float* __restrict__ A, const float* __restrict__ CB,
          const float* __restrict__ rr, const float* __restrict__ cn,
          ull* __restrict__ best) {
    __shared__ float As[2][BK][BM + APAD];
    __shared__ float Bs[2][BK][BN + BPAD];
    __shared__ ull sbest[BM];
    const int K = 256;
    int t = threadIdx.x;
    int tx4 = (t & 15) * 4, ty8 = (t >> 4) * 8;
    int rowBase = blockIdx.y * BM, colBase = blockIdx.x * BN;
    int ar = t >> 1, ak = (t & 1) * 8;
    int lc = t >> 1, kd = (t & 1) * 8;   // B loader: codebook rows (K-major)

    if (t < BM) sbest[t] = ~0ull;

    const float* Ap = A + (size_t)(rowBase + ar) * K + ak;
    const float* Cp = CB + (size_t)(colBase + lc) * K + kd;

    float2 acc[8][4];
    #pragma unroll
    for (int i = 0; i < 8; i++)
        #pragma unroll
        for (int j = 0; j < 4; j++) acc[i][j] = make_float2(0.f, 0.f);

    float4 ra0 = *(const float4*)(Ap);
    float4 ra1 = *(const float4*)(Ap + 4);
    float4 rb0 = *(const float4*)(Cp);
    float4 rb1 = *(const float4*)(Cp + 4);

    const int nk = K / BK;
    #pragma unroll 1
    for (int kt = 0; kt < nk; kt++) {
        int cur = kt & 1;
        As[cur][ak + 0][ar] = ra0.x; As[cur][ak + 1][ar] = ra0.y;
        As[cur][ak + 2][ar] = ra0.z; As[cur][ak + 3][ar] = ra0.w;
        As[cur][ak + 4][ar] = ra1.x; As[cur][ak + 5][ar] = ra1.y;
        As[cur][ak + 6][ar] = ra1.z; As[cur][ak + 7][ar] = ra1.w;
        Bs[cur][kd + 0][lc] = rb0.x; Bs[cur][kd + 1][lc] = rb0.y;
        Bs[cur][kd + 2][lc] = rb0.z; Bs[cur][kd + 3][lc] = rb0.w;
        Bs[cur][kd + 4][lc] = rb1.x; Bs[cur][kd + 5][lc] = rb1.y;
        Bs[cur][kd + 6][lc] = rb1.z; Bs[cur][kd + 7][lc] = rb1.w;
        __syncthreads();
        if (kt + 1 < nk) {
            ra0 = *(const float4*)(Ap + (kt + 1) * BK);
            ra1 = *(const float4*)(Ap + (kt + 1) * BK + 4);
            rb0 = *(const float4*)(Cp + (kt + 1) * BK);
            rb1 = *(const float4*)(Cp + (kt + 1) * BK + 4);
        }
        #pragma unroll
        for (int kk = 0; kk < BK; kk++) {
            float4 a0 = *(const float4*)&As[cur][kk][ty8];
            float4 a1 = *(const float4*)&As[cur][kk][ty8 + 4];
            float4 b0 = *(const float4*)&Bs[cur][kk][tx4];
            float4 b1 = *(const float4*)&Bs[cur][kk][tx4 + 64];
            MMA_STEP(acc, a0, a1, b0, b1)
        }
        __syncthreads();
    }

    float4 c0 = *(const float4*)(cn + colBase + tx4);
    float4 c1 = *(const float4*)(cn + colBase + tx4 + 64);
    float cc[8] = {c0.x, c0.y, c0.z, c0.w, c1.x, c1.y, c1.z, c1.w};
    int codes[8];
    #pragma unroll
    for (int j = 0; j < 4; j++) { codes[j] = colBase + tx4 + j; codes[4 + j] = colBase + tx4 + 64 + j; }
    #pragma unroll
    for (int i = 0; i < 8; i++) {
        float rrow = rr[rowBase + ty8 + i];
        float v[8] = {acc[i][0].x, acc[i][0].y, acc[i][1].x, acc[i][1].y,
                      acc[i][2].x, acc[i][2].y, acc[i][3].x, acc[i][3].y};
        ull mykey = ~0ull;
        #pragma unroll
        for (int j = 0; j < 8; j++) {
            float m2 = __fmul_rn(2.0f, v[j]);
            float t1 = __fsub_rn(rrow, m2);
            float d2 = __fadd_rn(t1, cc[j]);
            ull key = ((ull)__float_as_uint(d2) << 32) | (unsigned)codes[j];
            if (key < mykey) mykey = key;
        }
        atomicMin(&sbest[ty8 + i], mykey);
    }
    __syncthreads();
    if (t < BM) atomicMin(&best[rowBase + t], sbest[t]);
}

// ---------------- gather quantized (exact straight-through fp32) -------------
__global__ void k_vq_gather(const ull* __restrict__ best, const float* __restrict__ CB,
                            const float* __restrict__ enc, float* __restrict__ qn,
                            float* __restrict__ out_idx) {
    int n = blockIdx.x, c = threadIdx.x;
    int k = (int)(unsigned)(best[n] & 0xFFFFFFFFull);
    float q = CB[k * 256 + c];
    float inp = enc[n * 256 + c];
    qn[n * 256 + c] = __fsub_rn(__fadd_rn(q, inp), inp);
    if (c == 0) out_idx[n] = (float)k;
}

// ---------------- host side ---------------------------------------------------
static void run_block(const float* cur, float* nxt, const float* const* p, int off, int d,
                      float* LN, float* Cbuf, float* grn, float* nx) {
    const float* cw  = p[off + 0] + d * 256 * 49;
    const float* cbi = p[off + 1] + d * 256;
    const float* lng = p[off + 2] + d * 256;
    const float* lnb = p[off + 3] + d * 256;
    const float* w1  = p[off + 4] + d * 256 * 1024;
    const float* b1  = p[off + 5] + d * 1024;
    const float* gg  = p[off + 6] + d * 1024;
    const float* gb  = p[off + 7] + d * 1024;
    const float* w2  = p[off + 8] + d * 1024 * 256;
    const float* b2  = p[off + 9] + d * 256;
    k_conv_ln<<<NROW, 256>>>(cur, LN, cw, cbi, lng, lnb);
    k_fc1<<<dim3(INTER / BN, NROW / BM), 256>>>(LN, w1, b1, Cbuf);
    k_grn_sumsq<<<dim3(32, 8), dim3(32, 32)>>>(Cbuf, grn);
    k_grn_nx<<<BB, 1024>>>(grn, nx);
    k_fc2<<<dim3(CC / BN, NROW / BM), 256>>>(Cbuf, w2, nx, gg, gb, b2, cur, nxt);
}

extern "C" void kernel_launch(void* const* d_in, const int* in_sizes, int n_in,
                              void* d_out, int out_size) {
    const float* x  = (const float*)d_in[0];
    const float* cb = (const float*)d_in[1];
    const float* p[20];
    for (int i = 0; i < 20; i++) p[i] = (const float*)d_in[2 + i];
    float* out = (float*)d_out;

    float *A0, *A1, *LN, *Cbuf, *grn, *nx, *rr, *cn;
    ull* best;
    cudaGetSymbolAddress((void**)&A0,   g_A0);
    cudaGetSymbolAddress((void**)&A1,   g_A1);
    cudaGetSymbolAddress((void**)&LN,   g_LN);
    cudaGetSymbolAddress((void**)&Cbuf, g_C);
    cudaGetSymbolAddress((void**)&grn,  g_grn);
    cudaGetSymbolAddress((void**)&nx,   g_scl);
    cudaGetSymbolAddress((void**)&rr,   g_r);
    cudaGetSymbolAddress((void**)&cn,   g_cn);
    cudaGetSymbolAddress((void**)&best, g_best);

    dim3 tt(32, 8);
    k_transpose<<<dim3(128, 8, 8), tt>>>(x, A0, 256, 4096);

    float* cur = A0;
    float* nxt = A1;
    for (int d = 0; d < 2; d++) {
        run_block(cur, nxt, p, 0, d, LN, Cbuf, grn, nx);
        float* tmp = cur; cur = nxt; nxt = tmp;
    }
    k_rownorm256<<<NROW, 256>>>(cur, rr);
    k_rownorm256<<<KCB, 256>>>(cb, cn);
    cudaMemsetAsync(best, 0xFF, NROW * sizeof(ull));
    k_vq<<<dim3(KCB / BN, NROW / BM), 256>>>(cur, cb, rr, cn, best);
    k_vq_gather<<<NROW, 256>>>(best, cb, cur, nxt, out + 2 * NROW * CC);
    k_transpose<<<dim3(8, 128, 8), tt>>>(nxt, out, 4096, 256);
    cur = nxt;
    nxt = (cur == A0) ? A1 : A0;
    for (int d = 0; d < 2; d++) {
        run_block(cur, nxt, p, 10, d, LN, Cbuf, grn, nx);
        float* tmp = cur; cur = nxt; nxt = tmp;
    }
    k_transpose<<<dim3(8, 128, 8), tt>>>(cur, out + NROW * CC, 4096, 256);
}

// round 5
// speedup vs baseline: 1.4496x; 1.0481x over previous
#include <cuda_runtime.h>
#include <math.h>

// Problem constants
#define BB    8
#define CC    256
#define NROW  32768          // B*H*W
#define INTER 1024
#define KCB   1024

typedef unsigned long long ull;

// ---------------- scratch (device globals; no allocation at runtime) --------
__device__ float g_A0[NROW * CC];
__device__ float g_A1[NROW * CC];
__device__ float g_LN[NROW * CC];
__device__ float g_C [NROW * INTER];
__device__ float g_grn[BB * INTER];
__device__ float g_scl[BB * INTER];      // GRN nx per (b, k)
__device__ float g_r [NROW];
__device__ float g_cn[KCB];
__device__ ull   g_best[NROW];

// ---------------- packed fp32x2 FMA (bit-identical per lane to FFMA) --------
__device__ __forceinline__ ull dup2(float a) {
    ull r; asm("mov.b64 %0, {%1, %1};" : "=l"(r) : "f"(a)); return r;
}
__device__ __forceinline__ void fma2(float2& d, ull a2, const float2& b) {
    ull& dd = reinterpret_cast<ull&>(d);
    asm("fma.rn.f32x2 %0, %1, %2, %0;"
        : "+l"(dd)
        : "l"(a2), "l"(reinterpret_cast<const ull&>(b)));
}

// ---------------- XLA-style reductions (verified bit-exact; do not touch) ---
__device__ __forceinline__ float warp_red(float v) {
    #pragma unroll
    for (int off = 16; off > 0; off >>= 1)
        v = __fadd_rn(v, __shfl_down_sync(0xffffffffu, v, off));
    return v;
}

__device__ float block_red256(float v, float* s) {
    int t = threadIdx.x, w = t >> 5, l = t & 31;
    float ws = warp_red(v);
    if (l == 0) s[w] = ws;
    __syncthreads();
    if (w == 0) {
        float p = (l < 8) ? s[l] : 0.0f;
        p = warp_red(p);
        if (l == 0) s[8] = p;
    }
    __syncthreads();
    float r = s[8];
    __syncthreads();
    return r;
}

// exact serial replica of block_red256's cross-warp stage for 8 partials
// (valid only where si[] is valid, i.e. lane 0)
__device__ __forceinline__ float combine8(const float* si) {
    float t0 = __fadd_rn(si[0], si[4]);
    float t1 = __fadd_rn(si[1], si[5]);
    float t2 = __fadd_rn(si[2], si[6]);
    float t3 = __fadd_rn(si[3], si[7]);
    float u0 = __fadd_rn(t0, t2);
    float u1 = __fadd_rn(t1, t3);
    return __fadd_rn(u0, u1);
}

// ---------------- transpose: per-batch [R,S] -> [S,R] ------------------------
__global__ void k_transpose(const float* __restrict__ in, float* __restrict__ out,
                            int R, int S) {
    __shared__ float tile[32][33];
    int b = blockIdx.z;
    int base = b * R * S;
    int s0 = blockIdx.x * 32, r0 = blockIdx.y * 32;
    int sx = s0 + threadIdx.x;
    for (int i = threadIdx.y; i < 32; i += 8)
        tile[i][threadIdx.x] = in[base + (r0 + i) * S + sx];
    __syncthreads();
    int rx = r0 + threadIdx.x;
    for (int i = threadIdx.y; i < 32; i += 8)
        out[base + (s0 + i) * R + rx] = tile[threadIdx.x][i];
}

// ---------------- depthwise conv 7x7 + bias + LayerNorm ----------------------
// warp-per-pixel, lane l owns channels {32i + l}. warp_red(y_i) reproduces the
// original block_red256 warp-i tree exactly; combine8 reproduces its cross-warp
// stage exactly. Zero __syncthreads.
__global__ __launch_bounds__(256)
void k_conv_ln(const float* __restrict__ in, float* __restrict__ out,
               const float* __restrict__ cw, const float* __restrict__ cb,
               const float* __restrict__ lng, const float* __restrict__ lnb) {
    int p = blockIdx.x * 8 + (threadIdx.x >> 5);   // pixel 0..32767
    int l = threadIdx.x & 31;
    int b = p >> 12;
    int hw = p & 4095;
    int h = hw >> 6, w = hw & 63;
    const float* base = in + ((long)b << 12) * CC;

    float acc[8] = {0.f, 0.f, 0.f, 0.f, 0.f, 0.f, 0.f, 0.f};
    #pragma unroll
    for (int kh = 0; kh < 7; kh++) {
        int hh = h + kh - 3;
        if ((unsigned)hh >= 64u) continue;
        #pragma unroll
        for (int kw = 0; kw < 7; kw++) {
            int ww = w + kw - 3;
            if ((unsigned)ww >= 64u) continue;
            const float* xp = base + ((hh << 6) + ww) * CC + l;
            int tap = kh * 7 + kw;
            #pragma unroll
            for (int i = 0; i < 8; i++)
                acc[i] = __fmaf_rn(cw[(i * 32 + l) * 49 + tap], xp[i * 32], acc[i]);
        }
    }
    float y[8];
    #pragma unroll
    for (int i = 0; i < 8; i++) y[i] = __fadd_rn(acc[i], cb[i * 32 + l]);

    float si[8];
    #pragma unroll
    for (int i = 0; i < 8; i++) si[i] = warp_red(y[i]);
    float tot = combine8(si);
    tot = __shfl_sync(0xffffffffu, tot, 0);
    float mu = __fmul_rn(tot, 0.00390625f);

    float d[8];
    #pragma unroll
    for (int i = 0; i < 8; i++) d[i] = __fsub_rn(y[i], mu);
    #pragma unroll
    for (int i = 0; i < 8; i++) si[i] = warp_red(__fmul_rn(d[i], d[i]));
    float vt = combine8(si);
    vt = __shfl_sync(0xffffffffu, vt, 0);
    float var = __fmul_rn(vt, 0.00390625f);
    float rs = rsqrtf(__fadd_rn(var, 1e-5f));

    float* op = out + (size_t)p * CC;
    #pragma unroll
    for (int i = 0; i < 8; i++)
        op[i * 32 + l] = __fadd_rn(__fmul_rn(__fmul_rn(d[i], rs), lng[i * 32 + l]),
                                   lnb[i * 32 + l]);
}

// ============================================================================
// GEMM core: 128x128 CTA tile, 256 threads, 8x8 per thread, BK=16,
// double-buffered smem with ONE __syncthreads per k-tile,
// packed f32x2 (bit-exact k-ascending chains).
// ============================================================================
#define BM 128
#define BN 128
#define BK 16
#define APAD 4
#define BPAD 4

#define MMA_STEP(acc, a0, a1, b0, b1)                                         \
    {                                                                         \
        float2 p00 = make_float2(b0.x, b0.y), p01 = make_float2(b0.z, b0.w);  \
        float2 p10 = make_float2(b1.x, b1.y), p11 = make_float2(b1.z, b1.w);  \
        ull ap;                                                               \
        ap = dup2(a0.x); fma2(acc[0][0], ap, p00); fma2(acc[0][1], ap, p01);  \
                         fma2(acc[0][2], ap, p10); fma2(acc[0][3], ap, p11);  \
        ap = dup2(a0.y); fma2(acc[1][0], ap, p00); fma2(acc[1][1], ap, p01);  \
                         fma2(acc[1][2], ap, p10); fma2(acc[1][3], ap, p11);  \
        ap = dup2(a0.z); fma2(acc[2][0], ap, p00); fma2(acc[2][1], ap, p01);  \
                         fma2(acc[2][2], ap, p10); fma2(acc[2][3], ap, p11);  \
        ap = dup2(a0.w); fma2(acc[3][0], ap, p00); fma2(acc[3][1], ap, p01);  \
                         fma2(acc[3][2], ap, p10); fma2(acc[3][3], ap, p11);  \
        ap = dup2(a1.x); fma2(acc[4][0], ap, p00); fma2(acc[4][1], ap, p01);  \
                         fma2(acc[4][2], ap, p10); fma2(acc[4][3], ap, p11);  \
        ap = dup2(a1.y); fma2(acc[5][0], ap, p00); fma2(acc[5][1], ap, p01);  \
                         fma2(acc[5][2], ap, p10); fma2(acc[5][3], ap, p11);  \
        ap = dup2(a1.z); fma2(acc[6][0], ap, p00); fma2(acc[6][1], ap, p01);  \
                         fma2(acc[6][2], ap, p10); fma2(acc[6][3], ap, p11);  \
        ap = dup2(a1.w); fma2(acc[7][0], ap, p00); fma2(acc[7][1], ap, p01);  \
                         fma2(acc[7][2], ap, p10); fma2(acc[7][3], ap, p11);  \
    }

// ---------------- fc1: [32768,256] x [256,1024] + exact GELU ----------------
__global__ __launch_bounds__(256, 2)
void k_fc1(const float* __restrict__ A, const float* __restrict__ Wm,
           const float* __restrict__ bias, float* __restrict__ Out) {
    __shared__ float As[2][BK][BM + APAD];
    __shared__ float Bs[2][BK][BN + BPAD];
    const int K = 256, N = 1024;
    int t = threadIdx.x;
    int tx4 = (t & 15) * 4, ty8 = (t >> 4) * 8;
    int rowBase = blockIdx.y * BM, colBase = blockIdx.x * BN;
    int ar = t >> 1, ak = (t & 1) * 8;
    int bk = t >> 4, bn = (t & 15) * 4;

    const float* Ap = A + (size_t)(rowBase + ar) * K + ak;
    const float* Bp = Wm + (size_t)bk * N + colBase + bn;

    float2 acc[8][4];
    #pragma unroll
    for (int i = 0; i < 8; i++)
        #pragma unroll
        for (int j = 0; j < 4; j++) acc[i][j] = make_float2(0.f, 0.f);

    // prologue: tile 0 -> buf 0
    {
        float4 ra0 = *(const float4*)(Ap);
        float4 ra1 = *(const float4*)(Ap + 4);
        float4 rb0 = *(const float4*)(Bp);
        float4 rb1 = *(const float4*)(Bp + 64);
        As[0][ak + 0][ar] = ra0.x; As[0][ak + 1][ar] = ra0.y;
        As[0][ak + 2][ar] = ra0.z; As[0][ak + 3][ar] = ra0.w;
        As[0][ak + 4][ar] = ra1.x; As[0][ak + 5][ar] = ra1.y;
        As[0][ak + 6][ar] = ra1.z; As[0][ak + 7][ar] = ra1.w;
        *(float4*)&Bs[0][bk][bn]      = rb0;
        *(float4*)&Bs[0][bk][bn + 64] = rb1;
    }
    __syncthreads();

    const int nk = K / BK;
    #pragma unroll 1
    for (int kt = 0; kt < nk; kt++) {
        int cur = kt & 1;
        float4 ra0, ra1, rb0, rb1;
        bool more = (kt + 1 < nk);
        if (more) {
            ra0 = *(const float4*)(Ap + (kt + 1) * BK);
            ra1 = *(const float4*)(Ap + (kt + 1) * BK + 4);
            rb0 = *(const float4*)(Bp + (size_t)(kt + 1) * BK * N);
            rb1 = *(const float4*)(Bp + (size_t)(kt + 1) * BK * N + 64);
        }
        #pragma unroll
        for (int kk = 0; kk < BK; kk++) {
            float4 a0 = *(const float4*)&As[cur][kk][ty8];
            float4 a1 = *(const float4*)&As[cur][kk][ty8 + 4];
            float4 b0 = *(const float4*)&Bs[cur][kk][tx4];
            float4 b1 = *(const float4*)&Bs[cur][kk][tx4 + 64];
            MMA_STEP(acc, a0, a1, b0, b1)
        }
        if (more) {
            int nxt = cur ^ 1;
            As[nxt][ak + 0][ar] = ra0.x; As[nxt][ak + 1][ar] = ra0.y;
            As[nxt][ak + 2][ar] = ra0.z; As[nxt][ak + 3][ar] = ra0.w;
            As[nxt][ak + 4][ar] = ra1.x; As[nxt][ak + 5][ar] = ra1.y;
            As[nxt][ak + 6][ar] = ra1.z; As[nxt][ak + 7][ar] = ra1.w;
            *(float4*)&Bs[nxt][bk][bn]      = rb0;
            *(float4*)&Bs[nxt][bk][bn + 64] = rb1;
        }
        __syncthreads();
    }

    float4 bi0 = *(const float4*)(bias + colBase + tx4);
    float4 bi1 = *(const float4*)(bias + colBase + tx4 + 64);
    float bb[8] = {bi0.x, bi0.y, bi0.z, bi0.w, bi1.x, bi1.y, bi1.z, bi1.w};
    #pragma unroll
    for (int i = 0; i < 8; i++) {
        float v[8] = {acc[i][0].x, acc[i][0].y, acc[i][1].x, acc[i][1].y,
                      acc[i][2].x, acc[i][2].y, acc[i][3].x, acc[i][3].y};
        float o[8];
        #pragma unroll
        for (int j = 0; j < 8; j++) {
            float y = __fadd_rn(v[j], bb[j]);
            float e = erff(__fdiv_rn(y, 1.4142135623730951f));
            float u = __fadd_rn(e, 1.0f);
            o[j] = 0.5f * __fmul_rn(y, u);
        }
        float* dst = Out + (size_t)(rowBase + ty8 + i) * N + colBase + tx4;
        *(float4*)dst        = make_float4(o[0], o[1], o[2], o[3]);
        *(float4*)(dst + 64) = make_float4(o[4], o[5], o[6], o[7]);
    }
}

// ---------------- GRN sum of squares (bit-exact) -----------------------------
__global__ void k_grn_sumsq(const float* __restrict__ C, float* __restrict__ S) {
    __shared__ float sm[32][33];
    int b = blockIdx.y;
    int c = blockIdx.x * 32 + threadIdx.x;
    int ty = threadIdx.y;
    const float* base = C + ((long)b << 12) * 1024 + c;
    float acc = 0.0f;
    for (int tt = 0; tt < 128; tt++) {
        float v = base[(ty + (tt << 5)) * 1024];
        acc = __fadd_rn(acc, __fmul_rn(v, v));
    }
    sm[ty][threadIdx.x] = acc;
    __syncthreads();
    #pragma unroll
    for (int off = 16; off > 0; off >>= 1) {
        if (ty < off)
            sm[ty][threadIdx.x] = __fadd_rn(sm[ty][threadIdx.x], sm[ty + off][threadIdx.x]);
        __syncthreads();
    }
    if (ty == 0) S[b * 1024 + c] = sm[0][threadIdx.x];
}

// ---------------- GRN nx (bit-exact) -----------------------------------------
__global__ void k_grn_nx(const float* __restrict__ S, float* __restrict__ nxo) {
    __shared__ float s[40];
    int b = blockIdx.x, t = threadIdx.x, w = t >> 5, l = t & 31;
    float gx = sqrtf(S[b * 1024 + t]);
    float ws = warp_red(gx);
    if (l == 0) s[w] = ws;
    __syncthreads();
    if (w == 0) {
        float p = s[l];
        p = warp_red(p);
        if (l == 0) s[33] = p;
    }
    __syncthreads();
    float mean = __fmul_rn(s[33], 0.0009765625f);
    nxo[b * 1024 + t] = __fdiv_rn(gx, __fadd_rn(mean, 1e-6f));
}

// ---------------- fc2: [32768,1024] x [1024,256], GRN at A-load --------------
__device__ __forceinline__ void grn_chain8(float* ra, const float* nxp,
                                           const float* ggp, const float* gbp) {
    float4 n0 = *(const float4*)(nxp), n1 = *(const float4*)(nxp + 4);
    float4 g0 = *(const float4*)(ggp), g1 = *(const float4*)(ggp + 4);
    float4 h0 = *(const float4*)(gbp), h1 = *(const float4*)(gbp + 4);
    float nn[8] = {n0.x,n0.y,n0.z,n0.w,n1.x,n1.y,n1.z,n1.w};
    float gG[8] = {g0.x,g0.y,g0.z,g0.w,g1.x,g1.y,g1.z,g1.w};
    float gB[8] = {h0.x,h0.y,h0.z,h0.w,h1.x,h1.y,h1.z,h1.w};
    #pragma unroll
    for (int q = 0; q < 8; q++) {
        float t1 = __fmul_rn(ra[q], nn[q]);
        t1 = __fmul_rn(gG[q], t1);
        t1 = __fadd_rn(t1, gB[q]);
        ra[q] = __fadd_rn(t1, ra[q]);
    }
}

__global__ __launch_bounds__(256, 2)
void k_fc2(const float* __restrict__ A, const float* __restrict__ Wm,
           const float* __restrict__ nx, const float* __restrict__ gg,
           const float* __restrict__ gb, const float* __restrict__ b2,
           const float* __restrict__ res, float* __restrict__ Out) {
    __shared__ float As[2][BK][BM + APAD];
    __shared__ float Bs[2][BK][BN + BPAD];
    const int K = 1024, N = 256;
    int t = threadIdx.x;
    int tx4 = (t & 15) * 4, ty8 = (t >> 4) * 8;
    int rowBase = blockIdx.y * BM, colBase = blockIdx.x * BN;
    int bidx = rowBase >> 12;
    int ar = t >> 1, ak = (t & 1) * 8;
    int bk = t >> 4, bn = (t & 15) * 4;

    const float* Ap  = A + (size_t)(rowBase + ar) * K + ak;
    const float* Bp  = Wm + (size_t)bk * N + colBase + bn;
    const float* nxp = nx + bidx * 1024 + ak;
    const float* ggp = gg + ak;
    const float* gbp = gb + ak;

    float2 acc[8][4];
    #pragma unroll
    for (int i = 0; i < 8; i++)
        #pragma unroll
        for (int j = 0; j < 4; j++) acc[i][j] = make_float2(0.f, 0.f);

    // prologue
    {
        float ra[8];
        float4 v0 = *(const float4*)(Ap), v1 = *(const float4*)(Ap + 4);
        ra[0]=v0.x; ra[1]=v0.y; ra[2]=v0.z; ra[3]=v0.w;
        ra[4]=v1.x; ra[5]=v1.y; ra[6]=v1.z; ra[7]=v1.w;
        grn_chain8(ra, nxp, ggp, gbp);
        #pragma unroll
        for (int q = 0; q < 8; q++) As[0][ak + q][ar] = ra[q];
        *(float4*)&Bs[0][bk][bn]      = *(const float4*)(Bp);
        *(float4*)&Bs[0][bk][bn + 64] = *(const float4*)(Bp + 64);
    }
    __syncthreads();

    const int nk = K / BK;
    #pragma unroll 1
    for (int kt = 0; kt < nk; kt++) {
        int cur = kt & 1;
        bool more = (kt + 1 < nk);
        float ra[8];
        float4 rb0, rb1;
        if (more) {
            int ko = (kt + 1) * BK;
            float4 v0 = *(const float4*)(Ap + ko), v1 = *(const float4*)(Ap + ko + 4);
            ra[0]=v0.x; ra[1]=v0.y; ra[2]=v0.z; ra[3]=v0.w;
            ra[4]=v1.x; ra[5]=v1.y; ra[6]=v1.z; ra[7]=v1.w;
            grn_chain8(ra, nxp + ko, ggp + ko, gbp + ko);
            rb0 = *(const float4*)(Bp + (size_t)ko * N);
            rb1 = *(const float4*)(Bp + (size_t)ko * N + 64);
        }
        #pragma unroll
        for (int kk = 0; kk < BK; kk++) {
            float4 a0 = *(const float4*)&As[cur][kk][ty8];
            float4 a1 = *(const float4*)&As[cur][kk][ty8 + 4];
            float4 b0 = *(const float4*)&Bs[cur][kk][tx4];
            float4 b1 = *(const float4*)&Bs[cur][kk][tx4 + 64];
            MMA_STEP(acc, a0, a1, b0, b1)
        }
        if (more) {
            int nxtb = cur ^ 1;
            #pragma unroll
            for (int q = 0; q < 8; q++) As[nxtb][ak + q][ar] = ra[q];
            *(float4*)&Bs[nxtb][bk][bn]      = rb0;
            *(float4*)&Bs[nxtb][bk][bn + 64] = rb1;
        }
        __syncthreads();
    }

    float4 bi0 = *(const float4*)(b2 + colBase + tx4);
    float4 bi1 = *(const float4*)(b2 + colBase + tx4 + 64);
    float bb[8] = {bi0.x, bi0.y, bi0.z, bi0.w, bi1.x, bi1.y, bi1.z, bi1.w};
    #pragma unroll
    for (int i = 0; i < 8; i++) {
        size_t off = (size_t)(rowBase + ty8 + i) * N + colBase + tx4;
        float4 r0 = *(const float4*)(res + off);
        float4 r1 = *(const float4*)(res + off + 64);
        float rr[8] = {r0.x, r0.y, r0.z, r0.w, r1.x, r1.y, r1.z, r1.w};
        float v[8] = {acc[i][0].x, acc[i][0].y, acc[i][1].x, acc[i][1].y,
                      acc[i][2].x, acc[i][2].y, acc[i][3].x, acc[i][3].y};
        float o[8];
        #pragma unroll
        for (int j = 0; j < 8; j++)
            o[j] = __fadd_rn(__fadd_rn(v[j], bb[j]), rr[j]);
        *(float4*)(Out + off)      = make_float4(o[0], o[1], o[2], o[3]);
        *(float4*)(Out + off + 64) = make_float4(o[4], o[5], o[6], o[7]);
    }
}

// ---------------- row sum-of-squares (bit-exact) ------------------------------
__global__ void k_rownorm256(const float* __restrict__ X, float* __restrict__ R) {
    __shared__ float red[16];
    int n = blockIdx.x, c = threadIdx.x;
    float v = X[n * 256 + c];
    float s = block_red256(__fmul_rn(v, v), red);
    if (c == 0) R[n] = s;
}

// ---------------- VQ: scores GEMM + argmin (bit-exact d2) ---------------------
__global__ __launch_bounds__(256, 2)
void k_vq(const float* __restrict__ A, const float* __restrict__ CB,
          const float* __restrict__ rr, const float* __restrict__ cn,
          ull* __restrict__ best) {
    __shared__ float As[2][BK][BM + APAD];
    __shared__ float Bs[2][BK][BN + BPAD];
    __shared__ ull sbest[BM];
    const int K = 256;
    int t = threadIdx.x;
    int tx4 = (t & 15) * 4, ty8 = (t >> 4) * 8;
    int rowBase = blockIdx.y * BM, colBase = blockIdx.x * BN;
    int ar = t >> 1, ak = (t & 1) * 8;
    int lc = t >> 1, kd = (t & 1) * 8;   // B loader: codebook rows (K-major)

    if (t < BM) sbest[t] = ~0ull;

    const float* Ap = A + (size_t)(rowBase + ar) * K + ak;
    const float* Cp = CB + (size_t)(colBase + lc) * K + kd;

    float2 acc[8][4];
    #pragma unroll
    for (int i = 0; i < 8; i++)
        #pragma unroll
        for (int j = 0; j < 4; j++) acc[i][j] = make_float2(0.f, 0.f);

    // prologue
    {
        float4 ra0 = *(const float4*)(Ap);
        float4 ra1 = *(const float4*)(Ap + 4);
        float4 rb0 = *(const float4*)(Cp);
        float4 rb1 = *(const float4*)(Cp + 4);
        As[0][ak + 0][ar] = ra0.x; As[0][ak + 1][ar] = ra0.y;
        As[0][ak + 2][ar] = ra0.z; As[0][ak + 3][ar] = ra0.w;
        As[0][ak + 4][ar] = ra1.x; As[0][ak + 5][ar] = ra1.y;
        As[0][ak + 6][ar] = ra1.z; As[0][ak + 7][ar] = ra1.w;
        Bs[0][kd + 0][lc] = rb0.x; Bs[0][kd + 1][lc] = rb0.y;
        Bs[0][kd + 2][lc] = rb0.z; Bs[0][kd + 3][lc] = rb0.w;
        Bs[0][kd + 4][lc] = rb1.x; Bs[0][kd + 5][lc] = rb1.y;
        Bs[0][kd + 6][lc] = rb1.z; Bs[0][kd + 7][lc] = rb1.w;
    }
    __syncthreads();

    const int nk = K / BK;
    #pragma unroll 1
    for (int kt = 0; kt < nk; kt++) {
        int cur = kt & 1;
        bool more = (kt + 1 < nk);
        float4 ra0, ra1, rb0, rb1;
        if (more) {
            ra0 = *(const float4*)(Ap + (kt + 1) * BK);
            ra1 = *(const float4*)(Ap + (kt + 1) * BK + 4);
            rb0 = *(const float4*)(Cp + (kt + 1) * BK);
            rb1 = *(const float4*)(Cp + (kt + 1) * BK + 4);
        }
        #pragma unroll
        for (int kk = 0; kk < BK; kk++) {
            float4 a0 = *(const float4*)&As[cur][kk][ty8];
            float4 a1 = *(const float4*)&As[cur][kk][ty8 + 4];
            float4 b0 = *(const float4*)&Bs[cur][kk][tx4];
            float4 b1 = *(const float4*)&Bs[cur][kk][tx4 + 64];
            MMA_STEP(acc, a0, a1, b0, b1)
        }
        if (more) {
            int nxtb = cur ^ 1;
            As[nxtb][ak + 0][ar] = ra0.x; As[nxtb][ak + 1][ar] = ra0.y;
            As[nxtb][ak + 2][ar] = ra0.z; As[nxtb][ak + 3][ar] = ra0.w;
            As[nxtb][ak + 4][ar] = ra1.x; As[nxtb][ak + 5][ar] = ra1.y;
            As[nxtb][ak + 6][ar] = ra1.z; As[nxtb][ak + 7][ar] = ra1.w;
            Bs[nxtb][kd + 0][lc] = rb0.x; Bs[nxtb][kd + 1][lc] = rb0.y;
            Bs[nxtb][kd + 2][lc] = rb0.z; Bs[nxtb][kd + 3][lc] = rb0.w;
            Bs[nxtb][kd + 4][lc] = rb1.x; Bs[nxtb][kd + 5][lc] = rb1.y;
            Bs[nxtb][kd + 6][lc] = rb1.z; Bs[nxtb][kd + 7][lc] = rb1.w;
        }
        __syncthreads();
    }

    float4 c0 = *(const float4*)(cn + colBase + tx4);
    float4 c1 = *(const float4*)(cn + colBase + tx4 + 64);
    float cc[8] = {c0.x, c0.y, c0.z, c0.w, c1.x, c1.y, c1.z, c1.w};
    int codes[8];
    #pragma unroll
    for (int j = 0; j < 4; j++) { codes[j] = colBase + tx4 + j; codes[4 + j] = colBase + tx4 + 64 + j; }
    #pragma unroll
    for (int i = 0; i < 8; i++) {
        float rrow = rr[rowBase + ty8 + i];
        float v[8] = {acc[i][0].x, acc[i][0].y, acc[i][1].x, acc[i][1].y,
                      acc[i][2].x, acc[i][2].y, acc[i][3].x, acc[i][3].y};
        ull mykey = ~0ull;
        #pragma unroll
        for (int j = 0; j < 8; j++) {
            float m2 = __fmul_rn(2.0f, v[j]);
            float t1 = __fsub_rn(rrow, m2);
            float d2 = __fadd_rn(t1, cc[j]);
            ull key = ((ull)__float_as_uint(d2) << 32) | (unsigned)codes[j];
            if (key < mykey) mykey = key;
        }
        atomicMin(&sbest[ty8 + i], mykey);
    }
    __syncthreads();
    if (t < BM) atomicMin(&best[rowBase + t], sbest[t]);
}

// ---------------- gather quantized (exact straight-through fp32) -------------
__global__ void k_vq_gather(const ull* __restrict__ best, const float* __restrict__ CB,
                            const float* __restrict__ enc, float* __restrict__ qn,
                            float* __restrict__ out_idx) {
    int n = blockIdx.x, c = threadIdx.x;
    int k = (int)(unsigned)(best[n] & 0xFFFFFFFFull);
    float q = CB[k * 256 + c];
    float inp = enc[n * 256 + c];
    qn[n * 256 + c] = __fsub_rn(__fadd_rn(q, inp), inp);
    if (c == 0) out_idx[n] = (float)k;
}

// ---------------- host side ---------------------------------------------------
static void run_block(const float* cur, float* nxt, const float* const* p, int off, int d,
                      float* LN, float* Cbuf, float* grn, float* nx) {
    const float* cw  = p[off + 0] + d * 256 * 49;
    const float* cbi = p[off + 1] + d * 256;
    const float* lng = p[off + 2] + d * 256;
    const float* lnb = p[off + 3] + d * 256;
    const float* w1  = p[off + 4] + d * 256 * 1024;
    const float* b1  = p[off + 5] + d * 1024;
    const float* gg  = p[off + 6] + d * 1024;
    const float* gb  = p[off + 7] + d * 1024;
    const float* w2  = p[off + 8] + d * 1024 * 256;
    const float* b2  = p[off + 9] + d * 256;
    k_conv_ln<<<NROW / 8, 256>>>(cur, LN, cw, cbi, lng, lnb);
    k_fc1<<<dim3(INTER / BN, NROW / BM), 256>>>(LN, w1, b1, Cbuf);
    k_grn_sumsq<<<dim3(32, 8), dim3(32, 32)>>>(Cbuf, grn);
    k_grn_nx<<<BB, 1024>>>(grn, nx);
    k_fc2<<<dim3(CC / BN, NROW / BM), 256>>>(Cbuf, w2, nx, gg, gb, b2, cur, nxt);
}

extern "C" void kernel_launch(void* const* d_in, const int* in_sizes, int n_in,
                              void* d_out, int out_size) {
    const float* x  = (const float*)d_in[0];
    const float* cb = (const float*)d_in[1];
    const float* p[20];
    for (int i = 0; i < 20; i++) p[i] = (const float*)d_in[2 + i];
    float* out = (float*)d_out;

    float *A0, *A1, *LN, *Cbuf, *grn, *nx, *rr, *cn;
    ull* best;
    cudaGetSymbolAddress((void**)&A0,   g_A0);
    cudaGetSymbolAddress((void**)&A1,   g_A1);
    cudaGetSymbolAddress((void**)&LN,   g_LN);
    cudaGetSymbolAddress((void**)&Cbuf, g_C);
    cudaGetSymbolAddress((void**)&grn,  g_grn);
    cudaGetSymbolAddress((void**)&nx,   g_scl);
    cudaGetSymbolAddress((void**)&rr,   g_r);
    cudaGetSymbolAddress((void**)&cn,   g_cn);
    cudaGetSymbolAddress((void**)&best, g_best);

    dim3 tt(32, 8);
    k_transpose<<<dim3(128, 8, 8), tt>>>(x, A0, 256, 4096);

    float* cur = A0;
    float* nxt = A1;
    for (int d = 0; d < 2; d++) {
        run_block(cur, nxt, p, 0, d, LN, Cbuf, grn, nx);
        float* tmp = cur; cur = nxt; nxt = tmp;
    }
    k_rownorm256<<<NROW, 256>>>(cur, rr);
    k_rownorm256<<<KCB, 256>>>(cb, cn);
    cudaMemsetAsync(best, 0xFF, NROW * sizeof(ull));
    k_vq<<<dim3(KCB / BN, NROW / BM), 256>>>(cur, cb, rr, cn, best);
    k_vq_gather<<<NROW, 256>>>(best, cb, cur, nxt, out + 2 * NROW * CC);
    k_transpose<<<dim3(8, 128, 8), tt>>>(nxt, out, 4096, 256);
    cur = nxt;
    nxt = (cur == A0) ? A1 : A0;
    for (int d = 0; d < 2; d++) {
        run_block(cur, nxt, p, 10, d, LN, Cbuf, grn, nx);
        float* tmp = cur; cur = nxt; nxt = tmp;
    }
    k_transpose<<<dim3(8, 128, 8), tt>>>(cur, out + NROW * CC, 4096, 256);
}